// round 9
// baseline (speedup 1.0000x reference)
#include <cuda_runtime.h>
#include <cstdio>
#include <cstdlib>
#include <math.h>

#define BB 2
#define TT 4096
#define CC 1024
#define HH 16
#define DD 64
#define MM (BB*TT)   // 8192

// ---------------- scratch -----------------------------------------------------
__device__ float g_q[(size_t)MM * CC];    // raw projections [B,T,C]
__device__ float g_k[(size_t)MM * CC];
__device__ float g_v[(size_t)MM * CC];
__device__ float g_q2[(size_t)MM * CC];   // roped
__device__ float g_k2[(size_t)MM * CC];
__device__ float g_o[(size_t)MM * CC];    // attention out [B,T,C]
__device__ float g_dbg[16];

// inv-freq table: 10000^(-j/32) == 10^(-j/8)
__constant__ float c_inv[32] = {
    1.0f,            0.749894209f,   0.562341325f,   0.421696503f,
    0.316227766f,    0.237137371f,   0.177827941f,   0.133352143f,
    0.1f,            0.0749894209f,  0.0562341325f,  0.0421696503f,
    0.0316227766f,   0.0237137371f,  0.0177827941f,  0.0133352143f,
    0.01f,           0.00749894209f, 0.00562341325f, 0.00421696503f,
    0.00316227766f,  0.00237137371f, 0.00177827941f, 0.00133352143f,
    0.001f,          0.000749894209f,0.000562341325f,0.000421696503f,
    0.000316227766f, 0.000237137371f,0.000177827941f,0.000133352143f
};
static const float h_inv[32] = {
    1.0f,            0.749894209f,   0.562341325f,   0.421696503f,
    0.316227766f,    0.237137371f,   0.177827941f,   0.133352143f,
    0.1f,            0.0749894209f,  0.0562341325f,  0.0421696503f,
    0.0316227766f,   0.0237137371f,  0.0177827941f,  0.0133352143f,
    0.01f,           0.00749894209f, 0.00562341325f, 0.00421696503f,
    0.00316227766f,  0.00237137371f, 0.00177827941f, 0.00133352143f,
    0.001f,          0.000749894209f,0.000562341325f,0.000421696503f,
    0.000316227766f, 0.000237137371f,0.000177827941f,0.000133352143f
};

// range-reduce to [-pi,pi] then sincosf. NOTE CUDA signature: sincosf(x, SIN, COS).
__device__ __forceinline__ void safe_sincos(float ang, float* c, float* s)
{
    float k = rintf(ang * 0.159154943091895f);
    float r = fmaf(-k, 6.28318530717958f, ang);
    r = fmaf(-k, -1.7484556e-07f, r);     // compensate fl(2pi) residual
    sincosf(r, s, c);                     // sin first, cos second!
}

// ---------------- tiled GEMM: C[m,n] = sum_k A[m,k] * W[n,k] -----------------
#define GBM 128
#define GBN 128
#define GBK 16
#define GPAD 4

__global__ __launch_bounds__(256)
void tgemm(const float* __restrict__ A, const float* __restrict__ W,
           float* __restrict__ Cout)
{
    __shared__ float As[GBK][GBM + GPAD];
    __shared__ float Bs[GBK][GBN + GPAD];

    const int tid = threadIdx.x;
    const int tx = tid & 15;
    const int ty = tid >> 4;
    const int m0 = blockIdx.y * GBM;
    const int n0 = blockIdx.x * GBN;

    float acc[8][8] = {};

    for (int k0 = 0; k0 < CC; k0 += GBK) {
#pragma unroll
        for (int it = 0; it < 2; it++) {
            int lin = tid + it * 256;
            int row = lin >> 2;
            int c4  = (lin & 3) << 2;
            float4 a = *(const float4*)&A[(size_t)(m0 + row) * CC + k0 + c4];
            As[c4 + 0][row] = a.x; As[c4 + 1][row] = a.y;
            As[c4 + 2][row] = a.z; As[c4 + 3][row] = a.w;
            float4 b = *(const float4*)&W[(size_t)(n0 + row) * CC + k0 + c4];
            Bs[c4 + 0][row] = b.x; Bs[c4 + 1][row] = b.y;
            Bs[c4 + 2][row] = b.z; Bs[c4 + 3][row] = b.w;
        }
        __syncthreads();

#pragma unroll
        for (int kk = 0; kk < GBK; kk++) {
            float ar[8], br[8];
            float4 t4;
            t4 = *(const float4*)&As[kk][ty * 8];
            ar[0] = t4.x; ar[1] = t4.y; ar[2] = t4.z; ar[3] = t4.w;
            t4 = *(const float4*)&As[kk][ty * 8 + 4];
            ar[4] = t4.x; ar[5] = t4.y; ar[6] = t4.z; ar[7] = t4.w;
            t4 = *(const float4*)&Bs[kk][tx * 8];
            br[0] = t4.x; br[1] = t4.y; br[2] = t4.z; br[3] = t4.w;
            t4 = *(const float4*)&Bs[kk][tx * 8 + 4];
            br[4] = t4.x; br[5] = t4.y; br[6] = t4.z; br[7] = t4.w;
#pragma unroll
            for (int i = 0; i < 8; i++)
#pragma unroll
                for (int j = 0; j < 8; j++)
                    acc[i][j] += ar[i] * br[j];
        }
        __syncthreads();
    }

#pragma unroll
    for (int i = 0; i < 8; i++) {
        size_t m = (size_t)(m0 + ty * 8 + i);
        *(float4*)&Cout[m * CC + n0 + tx * 8] =
            make_float4(acc[i][0], acc[i][1], acc[i][2], acc[i][3]);
        *(float4*)&Cout[m * CC + n0 + tx * 8 + 4] =
            make_float4(acc[i][4], acc[i][5], acc[i][6], acc[i][7]);
    }
}

// ---------------- RoPE out-of-place -------------------------------------------
__global__ __launch_bounds__(512) void rope2()
{
    const int t = blockIdx.x;
    const int b = blockIdx.y;
    const int h = threadIdx.x >> 5;
    const int j = threadIdx.x & 31;

    float ang = (float)t * c_inv[j];
    float c, s;
    safe_sincos(ang, &c, &s);

    if (t == 1 && b == 0 && threadIdx.x < 4) {
        g_dbg[2 * threadIdx.x]     = c;
        g_dbg[2 * threadIdx.x + 1] = s;
    }

    const size_t row = ((size_t)b * TT + t) * CC;
    const int ch = h * DD + j;
    float a1 = g_q[row + ch], a2 = g_q[row + ch + 32];
    g_q2[row + ch]      = a1 * c - a2 * s;
    g_q2[row + ch + 32] = a2 * c + a1 * s;
    a1 = g_k[row + ch]; a2 = g_k[row + ch + 32];
    g_k2[row + ch]      = a1 * c - a2 * s;
    g_k2[row + ch + 32] = a2 * c + a1 * s;
}

// ---------------- flash attention (causal, fp32, 64x64 tiles) -----------------
__global__ __launch_bounds__(256)
void flash_kernel()
{
    __shared__ float sm3[3 * 64 * 64];   // 48 KB static
    float* Qs  = sm3;                    // [row][d]
    float* KtP = sm3 + 64 * 64;          // [d][key] then [row][key]
    float* Vs  = sm3 + 2 * 64 * 64;      // [key][d]

    const int tid = threadIdx.x;
    const int tx = tid & 15;
    const int ty = tid >> 4;
    const int bh = blockIdx.y;
    const int b = bh >> 4, h = bh & 15;
    const int qb = gridDim.x - 1 - blockIdx.x;   // longest first
    const int t0q = qb * 64;
    const size_t base = (size_t)b * TT * CC + h * DD;

    {
        const float sc = 0.125f;
#pragma unroll
        for (int it = 0; it < 4; it++) {
            int lin = tid + it * 256;
            int row = lin >> 4;
            int c4  = (lin & 15) << 2;
            float4 a = *(const float4*)&g_q2[base + (size_t)(t0q + row) * CC + c4];
            *(float4*)&Qs[row * 64 + c4] =
                make_float4(a.x * sc, a.y * sc, a.z * sc, a.w * sc);
        }
    }

    float m_i[4], l_i[4], oacc[4][4];
#pragma unroll
    for (int i = 0; i < 4; i++) {
        m_i[i] = -INFINITY; l_i[i] = 0.f;
#pragma unroll
        for (int j = 0; j < 4; j++) oacc[i][j] = 0.f;
    }

    for (int jt = 0; jt <= qb; jt++) {
        __syncthreads();
        const int t0k = jt * 64;
#pragma unroll
        for (int it = 0; it < 4; it++) {
            int lin = tid + it * 256;
            int row = lin >> 4;
            int c4  = (lin & 15) << 2;
            float4 kv = *(const float4*)&g_k2[base + (size_t)(t0k + row) * CC + c4];
            KtP[(c4 + 0) * 64 + row] = kv.x; KtP[(c4 + 1) * 64 + row] = kv.y;
            KtP[(c4 + 2) * 64 + row] = kv.z; KtP[(c4 + 3) * 64 + row] = kv.w;
            float4 vv = *(const float4*)&g_v[base + (size_t)(t0k + row) * CC + c4];
            *(float4*)&Vs[row * 64 + c4] = vv;
        }
        __syncthreads();

        float s4[4][4] = {};
#pragma unroll 4
        for (int d4 = 0; d4 < 16; d4++) {
            float qv[4][4], kv[4][4];
#pragma unroll
            for (int i = 0; i < 4; i++) {
                float4 t4 = *(const float4*)&Qs[(ty * 4 + i) * 64 + d4 * 4];
                qv[i][0] = t4.x; qv[i][1] = t4.y; qv[i][2] = t4.z; qv[i][3] = t4.w;
            }
#pragma unroll
            for (int s2 = 0; s2 < 4; s2++) {
                float4 t4 = *(const float4*)&KtP[(d4 * 4 + s2) * 64 + tx * 4];
                kv[s2][0] = t4.x; kv[s2][1] = t4.y; kv[s2][2] = t4.z; kv[s2][3] = t4.w;
            }
#pragma unroll
            for (int s2 = 0; s2 < 4; s2++)
#pragma unroll
                for (int i = 0; i < 4; i++)
#pragma unroll
                    for (int j = 0; j < 4; j++)
                        s4[i][j] += qv[i][s2] * kv[s2][j];
        }

        if (jt == qb) {
#pragma unroll
            for (int i = 0; i < 4; i++)
#pragma unroll
                for (int j = 0; j < 4; j++)
                    if (tx * 4 + j > ty * 4 + i) s4[i][j] = -INFINITY;
        }

        float p4[4][4];
#pragma unroll
        for (int i = 0; i < 4; i++) {
            float mx = s4[i][0];
#pragma unroll
            for (int j = 1; j < 4; j++) mx = fmaxf(mx, s4[i][j]);
#pragma unroll
            for (int off = 1; off < 16; off <<= 1)
                mx = fmaxf(mx, __shfl_xor_sync(0xffffffffu, mx, off, 16));
            float mnew  = fmaxf(m_i[i], mx);
            float alpha = __expf(m_i[i] - mnew);
            m_i[i] = mnew;
            float rs = 0.f;
#pragma unroll
            for (int j = 0; j < 4; j++) {
                p4[i][j] = __expf(s4[i][j] - mnew);
                rs += p4[i][j];
            }
#pragma unroll
            for (int off = 1; off < 16; off <<= 1)
                rs += __shfl_xor_sync(0xffffffffu, rs, off, 16);
            l_i[i] = l_i[i] * alpha + rs;
#pragma unroll
            for (int j = 0; j < 4; j++) oacc[i][j] *= alpha;
        }

        __syncthreads();
#pragma unroll
        for (int i = 0; i < 4; i++)
            *(float4*)&KtP[(ty * 4 + i) * 64 + tx * 4] =
                make_float4(p4[i][0], p4[i][1], p4[i][2], p4[i][3]);
        __syncthreads();

#pragma unroll 4
        for (int k4 = 0; k4 < 16; k4++) {
            float pv[4][4], vv[4][4];
#pragma unroll
            for (int i = 0; i < 4; i++) {
                float4 t4 = *(const float4*)&KtP[(ty * 4 + i) * 64 + k4 * 4];
                pv[i][0] = t4.x; pv[i][1] = t4.y; pv[i][2] = t4.z; pv[i][3] = t4.w;
            }
#pragma unroll
            for (int s2 = 0; s2 < 4; s2++) {
                float4 t4 = *(const float4*)&Vs[(k4 * 4 + s2) * 64 + tx * 4];
                vv[s2][0] = t4.x; vv[s2][1] = t4.y; vv[s2][2] = t4.z; vv[s2][3] = t4.w;
            }
#pragma unroll
            for (int s2 = 0; s2 < 4; s2++)
#pragma unroll
                for (int i = 0; i < 4; i++)
#pragma unroll
                    for (int j = 0; j < 4; j++)
                        oacc[i][j] += pv[i][s2] * vv[s2][j];
        }
    }

#pragma unroll
    for (int i = 0; i < 4; i++) {
        int t = t0q + ty * 4 + i;
        float inv = 1.f / l_i[i];
        *(float4*)&g_o[base + (size_t)t * CC + tx * 4] =
            make_float4(oacc[i][0] * inv, oacc[i][1] * inv,
                        oacc[i][2] * inv, oacc[i][3] * inv);
    }
}

// ---------------- launch -----------------------------------------------------
static float hA[1024], hB[1024], hC[1024], hD[1024], hE[4096], hV1[1024];

extern "C" void kernel_launch(void* const* d_in, const int* in_sizes, int n_in,
                              void* d_out, int out_size)
{
    const float* x  = (const float*)d_in[0];
    const float* Wq = (const float*)d_in[1];
    const float* Wk = (const float*)d_in[2];
    const float* Wv = (const float*)d_in[3];
    const float* Wo = (const float*)d_in[4];

    float *qp, *kp, *vp, *op;
    cudaGetSymbolAddress((void**)&qp, g_q);
    cudaGetSymbolAddress((void**)&kp, g_k);
    cudaGetSymbolAddress((void**)&vp, g_v);
    cudaGetSymbolAddress((void**)&op, g_o);

    dim3 gg(CC / GBN, MM / GBM);   // (8, 64)
    tgemm<<<gg, 256>>>(x, Wq, qp);
    tgemm<<<gg, 256>>>(x, Wk, kp);
    tgemm<<<gg, 256>>>(x, Wv, vp);

    rope2<<<dim3(TT, BB), 512>>>();

    flash_kernel<<<dim3(TT / 64, BB * HH), 256>>>();

    tgemm<<<gg, 256>>>(op, Wo, (float*)d_out);

    // ---- capture-guarded host verification; rc=3 only on failure ------------
    cudaStreamCaptureStatus csx = cudaStreamCaptureStatusNone;
    cudaStreamIsCapturing(0, &csx);
    if (csx != cudaStreamCaptureStatusNone) return;

    cudaError_t e = cudaDeviceSynchronize();
    if (e != cudaSuccess) {
        printf("[HC] pipeline error: %s\n", cudaGetErrorString(e));
        fflush(stdout); exit(3);
    }
    int bad = 0;

    // (1) in-kernel c/s at t=1 vs host libm
    float dbg[16];
    cudaMemcpyFromSymbol(dbg, g_dbg, 16 * 4, 0);
    for (int j = 0; j < 4; j++) {
        double ang = (double)h_inv[j];
        if (fabs(dbg[2 * j] - cos(ang)) > 2e-3 || fabs(dbg[2 * j + 1] - sin(ang)) > 2e-3) {
            printf("[HC] probe j=%d got c=%.6g s=%.6g exp c=%.6g s=%.6g\n",
                   j, dbg[2 * j], dbg[2 * j + 1], cos(ang), sin(ang));
            bad++;
        }
    }
    // (2) rope t=0 identity
    cudaMemcpyFromSymbol(hA, g_q, 1024 * 4, 0);
    cudaMemcpyFromSymbol(hB, g_q2, 1024 * 4, 0);
    for (int ch = 0; ch < 1024 && bad < 8; ch++)
        if (fabsf(hA[ch] - hB[ch]) > 1e-5f) {
            printf("[HC] rope t0 ch=%d q=%.6g q2=%.6g\n", ch, hA[ch], hB[ch]);
            bad++;
        }
    // (3) rope t=1 row vs host rotation
    cudaMemcpyFromSymbol(hA, g_q, 1024 * 4, (size_t)CC * 4);
    cudaMemcpyFromSymbol(hB, g_q2, 1024 * 4, (size_t)CC * 4);
    for (int h = 0; h < HH && bad < 8; h++)
        for (int j = 0; j < 32 && bad < 8; j++) {
            int ch = h * DD + j;
            double c = cos((double)h_inv[j]), s = sin((double)h_inv[j]);
            double e1 = hA[ch] * c - hA[ch + 32] * s;
            double e2 = hA[ch + 32] * c + hA[ch] * s;
            if (fabs(e1 - hB[ch]) > 1e-3 || fabs(e2 - hB[ch + 32]) > 1e-3) {
                printf("[HC] rope t1 h=%d j=%d got(%.6g,%.6g) exp(%.6g,%.6g)\n",
                       h, j, hB[ch], hB[ch + 32], e1, e2);
                bad++;
            }
        }
    // (4) attention t=0: o == v
    cudaMemcpyFromSymbol(hC, g_o, 1024 * 4, 0);
    cudaMemcpyFromSymbol(hD, g_v, 1024 * 4, 0);
    for (int ch = 0; ch < 1024 && bad < 8; ch++)
        if (fabsf(hC[ch] - hD[ch]) > 1e-3f * (fabsf(hD[ch]) + 1e-1f)) {
            printf("[HC] attn t0 ch=%d o=%.6g v=%.6g\n", ch, hC[ch], hD[ch]);
            bad++;
        }
    // (5) attention t=1: two-key softmax vs host
    {
        cudaMemcpyFromSymbol(hA, g_q2, 1024 * 4, (size_t)CC * 4);   // q2 row1
        cudaMemcpyFromSymbol(hB, g_k2, 1024 * 4, 0);                // k2 row0
        cudaMemcpyFromSymbol(hC, g_k2, 1024 * 4, (size_t)CC * 4);   // k2 row1
        cudaMemcpyFromSymbol(hD, g_v,  1024 * 4, 0);                // v row0
        cudaMemcpyFromSymbol(hV1, g_v, 1024 * 4, (size_t)CC * 4);   // v row1
        static float ho1[1024];
        cudaMemcpyFromSymbol(ho1, g_o, 1024 * 4, (size_t)CC * 4);   // o row1
        for (int h = 0; h < HH && bad < 8; h++) {
            double s0 = 0, s1 = 0;
            for (int d = 0; d < DD; d++) {
                s0 += (double)hA[h * DD + d] * hB[h * DD + d];
                s1 += (double)hA[h * DD + d] * hC[h * DD + d];
            }
            s0 *= 0.125; s1 *= 0.125;
            double m = s0 > s1 ? s0 : s1;
            double p0 = exp(s0 - m), p1 = exp(s1 - m), Z = p0 + p1;
            for (int d = 0; d < DD && bad < 8; d++) {
                double oe = (p0 * hD[h * DD + d] + p1 * hV1[h * DD + d]) / Z;
                if (fabs(oe - ho1[h * DD + d]) > 2e-3) {
                    printf("[HC] attn t1 h=%d d=%d got %.6g exp %.6g\n",
                           h, d, ho1[h * DD + d], oe);
                    bad++;
                }
            }
        }
    }
    // (6) final out[0,0:4] vs host dot
    {
        cudaMemcpyFromSymbol(hC, g_o, 1024 * 4, 0);
        cudaMemcpy(hE, Wo, 4096 * 4, cudaMemcpyDeviceToHost);
        float hout[4];
        cudaMemcpy(hout, d_out, 16, cudaMemcpyDeviceToHost);
        for (int r = 0; r < 4; r++) {
            double ex = 0;
            for (int k = 0; k < 1024; k++) ex += (double)hC[k] * hE[r * 1024 + k];
            if (fabs(ex - hout[r]) > 1e-3 * (fabs(ex) + 1.0)) {
                printf("[HC] out0 r=%d got %.6g exp %.6g\n", r, hout[r], ex);
                bad++;
            }
        }
    }
    if (bad) { printf("[HC] FAILED %d checks\n", bad); fflush(stdout); exit(3); }
}

// round 10
// speedup vs baseline: 1.2361x; 1.2361x over previous
#include <cuda_runtime.h>
#include <cstdio>
#include <cstdlib>
#include <math.h>

#define BB 2
#define TT 4096
#define CC 1024
#define HH 16
#define DD 64
#define MM (BB*TT)   // 8192

// ---------------- scratch -----------------------------------------------------
__device__ float g_q[(size_t)MM * CC];    // raw projections [B,T,C]
__device__ float g_k[(size_t)MM * CC];
__device__ float g_v[(size_t)MM * CC];
__device__ float g_q2[(size_t)MM * CC];   // roped
__device__ float g_k2[(size_t)MM * CC];
__device__ float g_o[(size_t)MM * CC];    // attention out [B,T,C]
__device__ float g_dbg[16];

// inv-freq table: 10000^(-j/32) == 10^(-j/8)
__constant__ float c_inv[32] = {
    1.0f,            0.749894209f,   0.562341325f,   0.421696503f,
    0.316227766f,    0.237137371f,   0.177827941f,   0.133352143f,
    0.1f,            0.0749894209f,  0.0562341325f,  0.0421696503f,
    0.0316227766f,   0.0237137371f,  0.0177827941f,  0.0133352143f,
    0.01f,           0.00749894209f, 0.00562341325f, 0.00421696503f,
    0.00316227766f,  0.00237137371f, 0.00177827941f, 0.00133352143f,
    0.001f,          0.000749894209f,0.000562341325f,0.000421696503f,
    0.000316227766f, 0.000237137371f,0.000177827941f,0.000133352143f
};
static const float h_inv[32] = {
    1.0f,            0.749894209f,   0.562341325f,   0.421696503f,
    0.316227766f,    0.237137371f,   0.177827941f,   0.133352143f,
    0.1f,            0.0749894209f,  0.0562341325f,  0.0421696503f,
    0.0316227766f,   0.0237137371f,  0.0177827941f,  0.0133352143f,
    0.01f,           0.00749894209f, 0.00562341325f, 0.00421696503f,
    0.00316227766f,  0.00237137371f, 0.00177827941f, 0.00133352143f,
    0.001f,          0.000749894209f,0.000562341325f,0.000421696503f,
    0.000316227766f, 0.000237137371f,0.000177827941f,0.000133352143f
};

// range-reduce to [-pi,pi] then sincosf. CUDA signature: sincosf(x, SIN, COS).
__device__ __forceinline__ void safe_sincos(float ang, float* c, float* s)
{
    float k = rintf(ang * 0.159154943091895f);
    float r = fmaf(-k, 6.28318530717958f, ang);
    r = fmaf(-k, -1.7484556e-07f, r);
    sincosf(r, s, c);                     // sin first, cos second!
}

__device__ __forceinline__ unsigned f2tf32(float x)
{
    unsigned r;
    asm("cvt.rna.tf32.f32 %0, %1;" : "=r"(r) : "f"(x));
    return r;
}

// ---------------- TF32 tensor-core GEMM: C[m,n] = sum_k A[m,k]*W[n,k] --------
// CTA 128x128, BK=16. 256 thr = 8 warps in 4(M)x2(N); warp tile 32x64.
// Atoms m16n8k8: per warp 2(M) x 8(N). smem k-major [BK][128+8] (pad 8 ->
// conflict-free fragment loads).
#define GBM 128
#define GBN 128
#define GBK 16
#define GPAD 8
#define LDA (GBM + GPAD)

__global__ __launch_bounds__(256)
void mgemm(const float* __restrict__ A, const float* __restrict__ W,
           float* __restrict__ Cout)
{
    __shared__ unsigned As[GBK][LDA];
    __shared__ unsigned Bs[GBK][LDA];

    const int tid  = threadIdx.x;
    const int lane = tid & 31;
    const int w    = tid >> 5;
    const int wm   = (w >> 1) * 32;       // warp M offset (0,32,64,96)
    const int wn   = (w & 1) * 64;        // warp N offset (0,64)
    const int m0 = blockIdx.y * GBM;
    const int n0 = blockIdx.x * GBN;

    const int lq = lane >> 2;             // quad id 0..7
    const int lr = lane & 3;              // thread in quad 0..3

    float c[2][8][4];
#pragma unroll
    for (int mi = 0; mi < 2; mi++)
#pragma unroll
        for (int ni = 0; ni < 8; ni++)
#pragma unroll
            for (int r = 0; r < 4; r++) c[mi][ni][r] = 0.f;

    for (int k0 = 0; k0 < CC; k0 += GBK) {
        // stage 128x16 of A and W, tf32-rounded, stored [k][m]
#pragma unroll
        for (int it = 0; it < 2; it++) {
            int lin = tid + it * 256;            // 0..511
            int row = lin >> 2;                  // 0..127
            int c4  = (lin & 3) << 2;            // 0,4,8,12
            float4 a = *(const float4*)&A[(size_t)(m0 + row) * CC + k0 + c4];
            As[c4 + 0][row] = f2tf32(a.x); As[c4 + 1][row] = f2tf32(a.y);
            As[c4 + 2][row] = f2tf32(a.z); As[c4 + 3][row] = f2tf32(a.w);
            float4 b = *(const float4*)&W[(size_t)(n0 + row) * CC + k0 + c4];
            Bs[c4 + 0][row] = f2tf32(b.x); Bs[c4 + 1][row] = f2tf32(b.y);
            Bs[c4 + 2][row] = f2tf32(b.z); Bs[c4 + 3][row] = f2tf32(b.w);
        }
        __syncthreads();

#pragma unroll
        for (int ks = 0; ks < GBK; ks += 8) {
            // A fragments: 2 m-atoms x 4 regs
            unsigned af[2][4];
#pragma unroll
            for (int mi = 0; mi < 2; mi++) {
                int rlo = wm + mi * 16 + lq;
                af[mi][0] = As[ks + lr][rlo];
                af[mi][1] = As[ks + lr][rlo + 8];
                af[mi][2] = As[ks + 4 + lr][rlo];
                af[mi][3] = As[ks + 4 + lr][rlo + 8];
            }
            // B fragments: 8 n-atoms x 2 regs
            unsigned bf[8][2];
#pragma unroll
            for (int ni = 0; ni < 8; ni++) {
                int col = wn + ni * 8 + lq;
                bf[ni][0] = Bs[ks + lr][col];
                bf[ni][1] = Bs[ks + 4 + lr][col];
            }
#pragma unroll
            for (int mi = 0; mi < 2; mi++)
#pragma unroll
                for (int ni = 0; ni < 8; ni++)
                    asm volatile(
                        "mma.sync.aligned.m16n8k8.row.col.f32.tf32.tf32.f32 "
                        "{%0,%1,%2,%3}, {%4,%5,%6,%7}, {%8,%9}, {%0,%1,%2,%3};"
                        : "+f"(c[mi][ni][0]), "+f"(c[mi][ni][1]),
                          "+f"(c[mi][ni][2]), "+f"(c[mi][ni][3])
                        : "r"(af[mi][0]), "r"(af[mi][1]),
                          "r"(af[mi][2]), "r"(af[mi][3]),
                          "r"(bf[ni][0]), "r"(bf[ni][1]));
        }
        __syncthreads();
    }

    // epilogue: c0,c1 at (row, 2*lr), c2,c3 at (row+8, 2*lr)
#pragma unroll
    for (int mi = 0; mi < 2; mi++) {
        int rlo = m0 + wm + mi * 16 + lq;
#pragma unroll
        for (int ni = 0; ni < 8; ni++) {
            int cc = n0 + wn + ni * 8 + 2 * lr;
            *(float2*)&Cout[(size_t)rlo * CC + cc] =
                make_float2(c[mi][ni][0], c[mi][ni][1]);
            *(float2*)&Cout[(size_t)(rlo + 8) * CC + cc] =
                make_float2(c[mi][ni][2], c[mi][ni][3]);
        }
    }
}

// ---------------- RoPE out-of-place -------------------------------------------
__global__ __launch_bounds__(512) void rope2()
{
    const int t = blockIdx.x;
    const int b = blockIdx.y;
    const int h = threadIdx.x >> 5;
    const int j = threadIdx.x & 31;

    float ang = (float)t * c_inv[j];
    float c, s;
    safe_sincos(ang, &c, &s);

    if (t == 1 && b == 0 && threadIdx.x < 4) {
        g_dbg[2 * threadIdx.x]     = c;
        g_dbg[2 * threadIdx.x + 1] = s;
    }

    const size_t row = ((size_t)b * TT + t) * CC;
    const int ch = h * DD + j;
    float a1 = g_q[row + ch], a2 = g_q[row + ch + 32];
    g_q2[row + ch]      = a1 * c - a2 * s;
    g_q2[row + ch + 32] = a2 * c + a1 * s;
    a1 = g_k[row + ch]; a2 = g_k[row + ch + 32];
    g_k2[row + ch]      = a1 * c - a2 * s;
    g_k2[row + ch + 32] = a2 * c + a1 * s;
}

// ---------------- flash attention (causal, fp32, 64x64 tiles) -----------------
__global__ __launch_bounds__(256)
void flash_kernel()
{
    __shared__ float sm3[3 * 64 * 64];   // 48 KB static
    float* Qs  = sm3;
    float* KtP = sm3 + 64 * 64;
    float* Vs  = sm3 + 2 * 64 * 64;

    const int tid = threadIdx.x;
    const int tx = tid & 15;
    const int ty = tid >> 4;
    const int bh = blockIdx.y;
    const int b = bh >> 4, h = bh & 15;
    const int qb = gridDim.x - 1 - blockIdx.x;
    const int t0q = qb * 64;
    const size_t base = (size_t)b * TT * CC + h * DD;

    {
        const float sc = 0.125f;
#pragma unroll
        for (int it = 0; it < 4; it++) {
            int lin = tid + it * 256;
            int row = lin >> 4;
            int c4  = (lin & 15) << 2;
            float4 a = *(const float4*)&g_q2[base + (size_t)(t0q + row) * CC + c4];
            *(float4*)&Qs[row * 64 + c4] =
                make_float4(a.x * sc, a.y * sc, a.z * sc, a.w * sc);
        }
    }

    float m_i[4], l_i[4], oacc[4][4];
#pragma unroll
    for (int i = 0; i < 4; i++) {
        m_i[i] = -INFINITY; l_i[i] = 0.f;
#pragma unroll
        for (int j = 0; j < 4; j++) oacc[i][j] = 0.f;
    }

    for (int jt = 0; jt <= qb; jt++) {
        __syncthreads();
        const int t0k = jt * 64;
#pragma unroll
        for (int it = 0; it < 4; it++) {
            int lin = tid + it * 256;
            int row = lin >> 4;
            int c4  = (lin & 15) << 2;
            float4 kv = *(const float4*)&g_k2[base + (size_t)(t0k + row) * CC + c4];
            KtP[(c4 + 0) * 64 + row] = kv.x; KtP[(c4 + 1) * 64 + row] = kv.y;
            KtP[(c4 + 2) * 64 + row] = kv.z; KtP[(c4 + 3) * 64 + row] = kv.w;
            float4 vv = *(const float4*)&g_v[base + (size_t)(t0k + row) * CC + c4];
            *(float4*)&Vs[row * 64 + c4] = vv;
        }
        __syncthreads();

        float s4[4][4] = {};
#pragma unroll 4
        for (int d4 = 0; d4 < 16; d4++) {
            float qv[4][4], kv[4][4];
#pragma unroll
            for (int i = 0; i < 4; i++) {
                float4 t4 = *(const float4*)&Qs[(ty * 4 + i) * 64 + d4 * 4];
                qv[i][0] = t4.x; qv[i][1] = t4.y; qv[i][2] = t4.z; qv[i][3] = t4.w;
            }
#pragma unroll
            for (int s2 = 0; s2 < 4; s2++) {
                float4 t4 = *(const float4*)&KtP[(d4 * 4 + s2) * 64 + tx * 4];
                kv[s2][0] = t4.x; kv[s2][1] = t4.y; kv[s2][2] = t4.z; kv[s2][3] = t4.w;
            }
#pragma unroll
            for (int s2 = 0; s2 < 4; s2++)
#pragma unroll
                for (int i = 0; i < 4; i++)
#pragma unroll
                    for (int j = 0; j < 4; j++)
                        s4[i][j] += qv[i][s2] * kv[s2][j];
        }

        if (jt == qb) {
#pragma unroll
            for (int i = 0; i < 4; i++)
#pragma unroll
                for (int j = 0; j < 4; j++)
                    if (tx * 4 + j > ty * 4 + i) s4[i][j] = -INFINITY;
        }

        float p4[4][4];
#pragma unroll
        for (int i = 0; i < 4; i++) {
            float mx = s4[i][0];
#pragma unroll
            for (int j = 1; j < 4; j++) mx = fmaxf(mx, s4[i][j]);
#pragma unroll
            for (int off = 1; off < 16; off <<= 1)
                mx = fmaxf(mx, __shfl_xor_sync(0xffffffffu, mx, off, 16));
            float mnew  = fmaxf(m_i[i], mx);
            float alpha = __expf(m_i[i] - mnew);
            m_i[i] = mnew;
            float rs = 0.f;
#pragma unroll
            for (int j = 0; j < 4; j++) {
                p4[i][j] = __expf(s4[i][j] - mnew);
                rs += p4[i][j];
            }
#pragma unroll
            for (int off = 1; off < 16; off <<= 1)
                rs += __shfl_xor_sync(0xffffffffu, rs, off, 16);
            l_i[i] = l_i[i] * alpha + rs;
#pragma unroll
            for (int j = 0; j < 4; j++) oacc[i][j] *= alpha;
        }

        __syncthreads();
#pragma unroll
        for (int i = 0; i < 4; i++)
            *(float4*)&KtP[(ty * 4 + i) * 64 + tx * 4] =
                make_float4(p4[i][0], p4[i][1], p4[i][2], p4[i][3]);
        __syncthreads();

#pragma unroll 4
        for (int k4 = 0; k4 < 16; k4++) {
            float pv[4][4], vv[4][4];
#pragma unroll
            for (int i = 0; i < 4; i++) {
                float4 t4 = *(const float4*)&KtP[(ty * 4 + i) * 64 + k4 * 4];
                pv[i][0] = t4.x; pv[i][1] = t4.y; pv[i][2] = t4.z; pv[i][3] = t4.w;
            }
#pragma unroll
            for (int s2 = 0; s2 < 4; s2++) {
                float4 t4 = *(const float4*)&Vs[(k4 * 4 + s2) * 64 + tx * 4];
                vv[s2][0] = t4.x; vv[s2][1] = t4.y; vv[s2][2] = t4.z; vv[s2][3] = t4.w;
            }
#pragma unroll
            for (int s2 = 0; s2 < 4; s2++)
#pragma unroll
                for (int i = 0; i < 4; i++)
#pragma unroll
                    for (int j = 0; j < 4; j++)
                        oacc[i][j] += pv[i][s2] * vv[s2][j];
        }
    }

#pragma unroll
    for (int i = 0; i < 4; i++) {
        int t = t0q + ty * 4 + i;
        float inv = 1.f / l_i[i];
        *(float4*)&g_o[base + (size_t)t * CC + tx * 4] =
            make_float4(oacc[i][0] * inv, oacc[i][1] * inv,
                        oacc[i][2] * inv, oacc[i][3] * inv);
    }
}

// ---------------- launch -----------------------------------------------------
static float hA[1024], hB[1024], hC[1024], hD[1024], hE[4096], hV1[1024];

extern "C" void kernel_launch(void* const* d_in, const int* in_sizes, int n_in,
                              void* d_out, int out_size)
{
    const float* x  = (const float*)d_in[0];
    const float* Wq = (const float*)d_in[1];
    const float* Wk = (const float*)d_in[2];
    const float* Wv = (const float*)d_in[3];
    const float* Wo = (const float*)d_in[4];

    float *qp, *kp, *vp, *op;
    cudaGetSymbolAddress((void**)&qp, g_q);
    cudaGetSymbolAddress((void**)&kp, g_k);
    cudaGetSymbolAddress((void**)&vp, g_v);
    cudaGetSymbolAddress((void**)&op, g_o);

    dim3 gg(CC / GBN, MM / GBM);   // (8, 64)
    mgemm<<<gg, 256>>>(x, Wq, qp);
    mgemm<<<gg, 256>>>(x, Wk, kp);
    mgemm<<<gg, 256>>>(x, Wv, vp);

    rope2<<<dim3(TT, BB), 512>>>();

    flash_kernel<<<dim3(TT / 64, BB * HH), 256>>>();

    mgemm<<<gg, 256>>>(op, Wo, (float*)d_out);

    // ---- capture-guarded host verification; rc=3 only on failure ------------
    cudaStreamCaptureStatus csx = cudaStreamCaptureStatusNone;
    cudaStreamIsCapturing(0, &csx);
    if (csx != cudaStreamCaptureStatusNone) return;

    cudaError_t e = cudaDeviceSynchronize();
    if (e != cudaSuccess) {
        printf("[HC] pipeline error: %s\n", cudaGetErrorString(e));
        fflush(stdout); exit(3);
    }
    int bad = 0;

    float dbg[16];
    cudaMemcpyFromSymbol(dbg, g_dbg, 16 * 4, 0);
    for (int j = 0; j < 4; j++) {
        double ang = (double)h_inv[j];
        if (fabs(dbg[2 * j] - cos(ang)) > 2e-3 || fabs(dbg[2 * j + 1] - sin(ang)) > 2e-3) {
            printf("[HC] probe j=%d got c=%.6g s=%.6g exp c=%.6g s=%.6g\n",
                   j, dbg[2 * j], dbg[2 * j + 1], cos(ang), sin(ang));
            bad++;
        }
    }
    cudaMemcpyFromSymbol(hA, g_q, 1024 * 4, 0);
    cudaMemcpyFromSymbol(hB, g_q2, 1024 * 4, 0);
    for (int ch = 0; ch < 1024 && bad < 8; ch++)
        if (fabsf(hA[ch] - hB[ch]) > 1e-5f) {
            printf("[HC] rope t0 ch=%d q=%.6g q2=%.6g\n", ch, hA[ch], hB[ch]);
            bad++;
        }
    cudaMemcpyFromSymbol(hA, g_q, 1024 * 4, (size_t)CC * 4);
    cudaMemcpyFromSymbol(hB, g_q2, 1024 * 4, (size_t)CC * 4);
    for (int h = 0; h < HH && bad < 8; h++)
        for (int j = 0; j < 32 && bad < 8; j++) {
            int ch = h * DD + j;
            double c = cos((double)h_inv[j]), s = sin((double)h_inv[j]);
            double e1 = hA[ch] * c - hA[ch + 32] * s;
            double e2 = hA[ch + 32] * c + hA[ch] * s;
            if (fabs(e1 - hB[ch]) > 1e-3 || fabs(e2 - hB[ch + 32]) > 1e-3) {
                printf("[HC] rope t1 h=%d j=%d got(%.6g,%.6g) exp(%.6g,%.6g)\n",
                       h, j, hB[ch], hB[ch + 32], e1, e2);
                bad++;
            }
        }
    cudaMemcpyFromSymbol(hC, g_o, 1024 * 4, 0);
    cudaMemcpyFromSymbol(hD, g_v, 1024 * 4, 0);
    for (int ch = 0; ch < 1024 && bad < 8; ch++)
        if (fabsf(hC[ch] - hD[ch]) > 1e-3f * (fabsf(hD[ch]) + 1e-1f)) {
            printf("[HC] attn t0 ch=%d o=%.6g v=%.6g\n", ch, hC[ch], hD[ch]);
            bad++;
        }
    {
        cudaMemcpyFromSymbol(hA, g_q2, 1024 * 4, (size_t)CC * 4);
        cudaMemcpyFromSymbol(hB, g_k2, 1024 * 4, 0);
        cudaMemcpyFromSymbol(hC, g_k2, 1024 * 4, (size_t)CC * 4);
        cudaMemcpyFromSymbol(hD, g_v,  1024 * 4, 0);
        cudaMemcpyFromSymbol(hV1, g_v, 1024 * 4, (size_t)CC * 4);
        static float ho1[1024];
        cudaMemcpyFromSymbol(ho1, g_o, 1024 * 4, (size_t)CC * 4);
        for (int h = 0; h < HH && bad < 8; h++) {
            double s0 = 0, s1 = 0;
            for (int d = 0; d < DD; d++) {
                s0 += (double)hA[h * DD + d] * hB[h * DD + d];
                s1 += (double)hA[h * DD + d] * hC[h * DD + d];
            }
            s0 *= 0.125; s1 *= 0.125;
            double m = s0 > s1 ? s0 : s1;
            double p0 = exp(s0 - m), p1 = exp(s1 - m), Z = p0 + p1;
            for (int d = 0; d < DD && bad < 8; d++) {
                double oe = (p0 * hD[h * DD + d] + p1 * hV1[h * DD + d]) / Z;
                if (fabs(oe - ho1[h * DD + d]) > 2e-3) {
                    printf("[HC] attn t1 h=%d d=%d got %.6g exp %.6g\n",
                           h, d, ho1[h * DD + d], oe);
                    bad++;
                }
            }
        }
    }
    {
        cudaMemcpyFromSymbol(hC, g_o, 1024 * 4, 0);
        cudaMemcpy(hE, Wo, 4096 * 4, cudaMemcpyDeviceToHost);
        float hout[4];
        cudaMemcpy(hout, d_out, 16, cudaMemcpyDeviceToHost);
        for (int r = 0; r < 4; r++) {
            double ex = 0;
            for (int k = 0; k < 1024; k++) ex += (double)hC[k] * hE[r * 1024 + k];
            if (fabs(ex - hout[r]) > 2e-3 * (fabs(ex) + 1.0)) {
                printf("[HC] out0 r=%d got %.6g exp %.6g\n", r, hout[r], ex);
                bad++;
            }
        }
    }
    if (bad) { printf("[HC] FAILED %d checks\n", bad); fflush(stdout); exit(3); }
}

// round 11
// speedup vs baseline: 2.5642x; 2.0744x over previous
#include <cuda_runtime.h>
#include <cstdio>
#include <cstdlib>
#include <math.h>

#define BB 2
#define TT 4096
#define CC 1024
#define HH 16
#define DD 64
#define MM (BB*TT)   // 8192

// ---------------- scratch -----------------------------------------------------
__device__ float g_q[(size_t)MM * CC];
__device__ float g_k[(size_t)MM * CC];
__device__ float g_v[(size_t)MM * CC];
__device__ float g_q2[(size_t)MM * CC];
__device__ float g_k2[(size_t)MM * CC];
__device__ float g_o[(size_t)MM * CC];
__device__ float g_dbg[16];

__constant__ float c_inv[32] = {
    1.0f,            0.749894209f,   0.562341325f,   0.421696503f,
    0.316227766f,    0.237137371f,   0.177827941f,   0.133352143f,
    0.1f,            0.0749894209f,  0.0562341325f,  0.0421696503f,
    0.0316227766f,   0.0237137371f,  0.0177827941f,  0.0133352143f,
    0.01f,           0.00749894209f, 0.00562341325f, 0.00421696503f,
    0.00316227766f,  0.00237137371f, 0.00177827941f, 0.00133352143f,
    0.001f,          0.000749894209f,0.000562341325f,0.000421696503f,
    0.000316227766f, 0.000237137371f,0.000177827941f,0.000133352143f
};
static const float h_inv[32] = {
    1.0f,            0.749894209f,   0.562341325f,   0.421696503f,
    0.316227766f,    0.237137371f,   0.177827941f,   0.133352143f,
    0.1f,            0.0749894209f,  0.0562341325f,  0.0421696503f,
    0.0316227766f,   0.0237137371f,  0.0177827941f,  0.0133352143f,
    0.01f,           0.00749894209f, 0.00562341325f, 0.00421696503f,
    0.00316227766f,  0.00237137371f, 0.00177827941f, 0.00133352143f,
    0.001f,          0.000749894209f,0.000562341325f,0.000421696503f,
    0.000316227766f, 0.000237137371f,0.000177827941f,0.000133352143f
};

__device__ __forceinline__ void safe_sincos(float ang, float* c, float* s)
{
    float k = rintf(ang * 0.159154943091895f);
    float r = fmaf(-k, 6.28318530717958f, ang);
    r = fmaf(-k, -1.7484556e-07f, r);
    sincosf(r, s, c);                     // CUDA: sin first, cos second!
}

__device__ __forceinline__ unsigned f2tf32(float x)
{
    unsigned r;
    asm("cvt.rna.tf32.f32 %0, %1;" : "=r"(r) : "f"(x));
    return r;
}

// FMA-only 2^y for y <= 0 (clamped at -100); no MUFU.
__device__ __forceinline__ float fexp2(float y)
{
    y = fmaxf(y, -100.0f);
    float z = y + 12582912.0f;                 // 1.5*2^23 magic
    int   i = __float_as_int(z) - 0x4B400000;  // round(y)
    float f = y - (z - 12582912.0f);           // f in [-0.5, 0.5]
    float p =           0.0013333558f;
    p = fmaf(p, f, 0.0096181291f);
    p = fmaf(p, f, 0.0555041087f);
    p = fmaf(p, f, 0.2402265069f);
    p = fmaf(p, f, 0.6931471806f);
    p = fmaf(p, f, 1.0f);
    return __int_as_float(__float_as_int(p) + (i << 23));
}

#define MMA_TF32(acc, a0, a1, a2, a3, b0, b1)                                  \
    asm volatile(                                                              \
        "mma.sync.aligned.m16n8k8.row.col.f32.tf32.tf32.f32 "                  \
        "{%0,%1,%2,%3}, {%4,%5,%6,%7}, {%8,%9}, {%0,%1,%2,%3};"                \
        : "+f"(acc[0]), "+f"(acc[1]), "+f"(acc[2]), "+f"(acc[3])               \
        : "r"(a0), "r"(a1), "r"(a2), "r"(a3), "r"(b0), "r"(b1))

// ---------------- TF32 tensor-core GEMM (verified R10) -----------------------
#define GBM 128
#define GBN 128
#define GBK 16
#define GPAD 8
#define LDA (GBM + GPAD)

__global__ __launch_bounds__(256)
void mgemm(const float* __restrict__ A, const float* __restrict__ W,
           float* __restrict__ Cout)
{
    __shared__ unsigned As[GBK][LDA];
    __shared__ unsigned Bs[GBK][LDA];

    const int tid  = threadIdx.x;
    const int lane = tid & 31;
    const int w    = tid >> 5;
    const int wm   = (w >> 1) * 32;
    const int wn   = (w & 1) * 64;
    const int m0 = blockIdx.y * GBM;
    const int n0 = blockIdx.x * GBN;
    const int lq = lane >> 2;
    const int lr = lane & 3;

    float c[2][8][4];
#pragma unroll
    for (int mi = 0; mi < 2; mi++)
#pragma unroll
        for (int ni = 0; ni < 8; ni++)
#pragma unroll
            for (int r = 0; r < 4; r++) c[mi][ni][r] = 0.f;

    for (int k0 = 0; k0 < CC; k0 += GBK) {
#pragma unroll
        for (int it = 0; it < 2; it++) {
            int lin = tid + it * 256;
            int row = lin >> 2;
            int c4  = (lin & 3) << 2;
            float4 a = *(const float4*)&A[(size_t)(m0 + row) * CC + k0 + c4];
            As[c4 + 0][row] = f2tf32(a.x); As[c4 + 1][row] = f2tf32(a.y);
            As[c4 + 2][row] = f2tf32(a.z); As[c4 + 3][row] = f2tf32(a.w);
            float4 b = *(const float4*)&W[(size_t)(n0 + row) * CC + k0 + c4];
            Bs[c4 + 0][row] = f2tf32(b.x); Bs[c4 + 1][row] = f2tf32(b.y);
            Bs[c4 + 2][row] = f2tf32(b.z); Bs[c4 + 3][row] = f2tf32(b.w);
        }
        __syncthreads();

#pragma unroll
        for (int ks = 0; ks < GBK; ks += 8) {
            unsigned af[2][4];
#pragma unroll
            for (int mi = 0; mi < 2; mi++) {
                int rlo = wm + mi * 16 + lq;
                af[mi][0] = As[ks + lr][rlo];
                af[mi][1] = As[ks + lr][rlo + 8];
                af[mi][2] = As[ks + 4 + lr][rlo];
                af[mi][3] = As[ks + 4 + lr][rlo + 8];
            }
            unsigned bf[8][2];
#pragma unroll
            for (int ni = 0; ni < 8; ni++) {
                int col = wn + ni * 8 + lq;
                bf[ni][0] = Bs[ks + lr][col];
                bf[ni][1] = Bs[ks + 4 + lr][col];
            }
#pragma unroll
            for (int mi = 0; mi < 2; mi++)
#pragma unroll
                for (int ni = 0; ni < 8; ni++)
                    MMA_TF32(c[mi][ni], af[mi][0], af[mi][1], af[mi][2], af[mi][3],
                             bf[ni][0], bf[ni][1]);
        }
        __syncthreads();
    }

#pragma unroll
    for (int mi = 0; mi < 2; mi++) {
        int rlo = m0 + wm + mi * 16 + lq;
#pragma unroll
        for (int ni = 0; ni < 8; ni++) {
            int cc = n0 + wn + ni * 8 + 2 * lr;
            *(float2*)&Cout[(size_t)rlo * CC + cc] =
                make_float2(c[mi][ni][0], c[mi][ni][1]);
            *(float2*)&Cout[(size_t)(rlo + 8) * CC + cc] =
                make_float2(c[mi][ni][2], c[mi][ni][3]);
        }
    }
}

// ---------------- RoPE --------------------------------------------------------
__global__ __launch_bounds__(512) void rope2()
{
    const int t = blockIdx.x;
    const int b = blockIdx.y;
    const int h = threadIdx.x >> 5;
    const int j = threadIdx.x & 31;

    float ang = (float)t * c_inv[j];
    float c, s;
    safe_sincos(ang, &c, &s);

    if (t == 1 && b == 0 && threadIdx.x < 4) {
        g_dbg[2 * threadIdx.x]     = c;
        g_dbg[2 * threadIdx.x + 1] = s;
    }

    const size_t row = ((size_t)b * TT + t) * CC;
    const int ch = h * DD + j;
    float a1 = g_q[row + ch], a2 = g_q[row + ch + 32];
    g_q2[row + ch]      = a1 * c - a2 * s;
    g_q2[row + ch + 32] = a2 * c + a1 * s;
    a1 = g_k[row + ch]; a2 = g_k[row + ch + 32];
    g_k2[row + ch]      = a1 * c - a2 * s;
    g_k2[row + ch + 32] = a2 * c + a1 * s;
}

// ---------------- tensor-core flash attention --------------------------------
// 128 thr = 4 warps; warp w owns q-rows [w*16, w*16+16). Tiles 64x64.
// Qs/Ks/Ps stride 68, Vs stride 72 (conflict-free fragment LDS).
#define QLD 68
#define VLD 72
#define FLASH_SMEM ((3 * 64 * QLD + 64 * VLD) * 4)   // 70656 B

__global__ __launch_bounds__(128)
void flash_tc()
{
    extern __shared__ unsigned fsm[];
    unsigned* Qs = fsm;                    // tf32 [row][d]
    unsigned* Ks = fsm + 64 * QLD;         // tf32 [key][d]
    unsigned* Ps = fsm + 2 * 64 * QLD;     // tf32 [row][key] (warp-private rows)
    unsigned* Vs = fsm + 3 * 64 * QLD;     // tf32 [key][d]

    const int tid  = threadIdx.x;
    const int lane = tid & 31;
    const int strip = (tid >> 5) * 16;
    const int lq = lane >> 2, lr = lane & 3;

    const int bh = blockIdx.y;
    const int b = bh >> 4, h = bh & 15;
    const int qb = gridDim.x - 1 - blockIdx.x;   // longest first
    const int t0q = qb * 64;
    const size_t base = (size_t)b * TT * CC + h * DD;

    // Q staged pre-scaled into log2 domain: S' = (q.k)/8 * log2(e)
    const float qsc = 0.125f * 1.44269504f;
#pragma unroll
    for (int it = 0; it < 8; it++) {
        int lin = tid + it * 128;
        int row = lin >> 4, c4 = (lin & 15) << 2;
        float4 a = *(const float4*)&g_q2[base + (size_t)(t0q + row) * CC + c4];
        *(uint4*)&Qs[row * QLD + c4] =
            make_uint4(f2tf32(a.x * qsc), f2tf32(a.y * qsc),
                       f2tf32(a.z * qsc), f2tf32(a.w * qsc));
    }

    float m_i[2] = {-INFINITY, -INFINITY};
    float l_i[2] = {0.f, 0.f};
    float oa[8][4];
#pragma unroll
    for (int ni = 0; ni < 8; ni++)
#pragma unroll
        for (int r = 0; r < 4; r++) oa[ni][r] = 0.f;

    for (int jt = 0; jt <= qb; jt++) {
        __syncthreads();                      // Ks/Vs reuse + Q visible (it 0)
        const int t0k = jt * 64;
#pragma unroll
        for (int it = 0; it < 8; it++) {
            int lin = tid + it * 128;
            int row = lin >> 4, c4 = (lin & 15) << 2;
            float4 kv = *(const float4*)&g_k2[base + (size_t)(t0k + row) * CC + c4];
            *(uint4*)&Ks[row * QLD + c4] =
                make_uint4(f2tf32(kv.x), f2tf32(kv.y), f2tf32(kv.z), f2tf32(kv.w));
            float4 vv = *(const float4*)&g_v[base + (size_t)(t0k + row) * CC + c4];
            *(uint4*)&Vs[row * VLD + c4] =
                make_uint4(f2tf32(vv.x), f2tf32(vv.y), f2tf32(vv.z), f2tf32(vv.w));
        }
        __syncthreads();

        // S' = Qs @ Ks^T   (16 rows x 64 keys per warp)
        float sa[8][4];
#pragma unroll
        for (int ni = 0; ni < 8; ni++)
#pragma unroll
            for (int r = 0; r < 4; r++) sa[ni][r] = 0.f;

#pragma unroll
        for (int ks = 0; ks < 64; ks += 8) {
            unsigned a0 = Qs[(strip + lq) * QLD + ks + lr];
            unsigned a1 = Qs[(strip + lq + 8) * QLD + ks + lr];
            unsigned a2 = Qs[(strip + lq) * QLD + ks + 4 + lr];
            unsigned a3 = Qs[(strip + lq + 8) * QLD + ks + 4 + lr];
#pragma unroll
            for (int ni = 0; ni < 8; ni++) {
                unsigned b0 = Ks[(ni * 8 + lq) * QLD + ks + lr];
                unsigned b1 = Ks[(ni * 8 + lq) * QLD + ks + 4 + lr];
                MMA_TF32(sa[ni], a0, a1, a2, a3, b0, b1);
            }
        }

        if (jt == qb) {                        // causal mask (tile-local coords)
            int r0 = strip + lq, r1 = r0 + 8;
#pragma unroll
            for (int ni = 0; ni < 8; ni++) {
                int col = ni * 8 + 2 * lr;
                if (col     > r0) sa[ni][0] = -1e30f;
                if (col + 1 > r0) sa[ni][1] = -1e30f;
                if (col     > r1) sa[ni][2] = -1e30f;
                if (col + 1 > r1) sa[ni][3] = -1e30f;
            }
        }

        // online softmax in exp2 domain; quad (lr) holds the row
#pragma unroll
        for (int r = 0; r < 2; r++) {
            float mx = fmaxf(sa[0][2 * r], sa[0][2 * r + 1]);
#pragma unroll
            for (int ni = 1; ni < 8; ni++)
                mx = fmaxf(mx, fmaxf(sa[ni][2 * r], sa[ni][2 * r + 1]));
            mx = fmaxf(mx, __shfl_xor_sync(0xffffffffu, mx, 1));
            mx = fmaxf(mx, __shfl_xor_sync(0xffffffffu, mx, 2));
            float mnew  = fmaxf(m_i[r], mx);
            float alpha = fexp2(m_i[r] - mnew);
            m_i[r] = mnew;
            float sum = 0.f;
            int prow = (strip + lq + 8 * r) * QLD;
#pragma unroll
            for (int ni = 0; ni < 8; ni++) {
                float p0 = fexp2(sa[ni][2 * r] - mnew);
                float p1 = fexp2(sa[ni][2 * r + 1] - mnew);
                sum += p0 + p1;
                Ps[prow + ni * 8 + 2 * lr]     = f2tf32(p0);
                Ps[prow + ni * 8 + 2 * lr + 1] = f2tf32(p1);
            }
            sum += __shfl_xor_sync(0xffffffffu, sum, 1);
            sum += __shfl_xor_sync(0xffffffffu, sum, 2);
            l_i[r] = l_i[r] * alpha + sum;
#pragma unroll
            for (int ni = 0; ni < 8; ni++) {
                oa[ni][2 * r]     *= alpha;
                oa[ni][2 * r + 1] *= alpha;
            }
        }
        __syncwarp();                          // Ps rows are warp-private

        // O += Ps @ Vs
#pragma unroll
        for (int ks = 0; ks < 64; ks += 8) {
            unsigned a0 = Ps[(strip + lq) * QLD + ks + lr];
            unsigned a1 = Ps[(strip + lq + 8) * QLD + ks + lr];
            unsigned a2 = Ps[(strip + lq) * QLD + ks + 4 + lr];
            unsigned a3 = Ps[(strip + lq + 8) * QLD + ks + 4 + lr];
#pragma unroll
            for (int ni = 0; ni < 8; ni++) {
                unsigned b0 = Vs[(ks + lr) * VLD + ni * 8 + lq];
                unsigned b1 = Vs[(ks + 4 + lr) * VLD + ni * 8 + lq];
                MMA_TF32(oa[ni], a0, a1, a2, a3, b0, b1);
            }
        }
    }

    // epilogue
    float inv0 = 1.f / l_i[0], inv1 = 1.f / l_i[1];
    int t0 = t0q + strip + lq;
#pragma unroll
    for (int ni = 0; ni < 8; ni++) {
        int d = ni * 8 + 2 * lr;
        *(float2*)&g_o[base + (size_t)t0 * CC + d] =
            make_float2(oa[ni][0] * inv0, oa[ni][1] * inv0);
        *(float2*)&g_o[base + (size_t)(t0 + 8) * CC + d] =
            make_float2(oa[ni][2] * inv1, oa[ni][3] * inv1);
    }
}

// ---------------- launch -----------------------------------------------------
static float hA[1024], hB[1024], hC[1024], hD[1024], hE[4096], hV1[1024];

extern "C" void kernel_launch(void* const* d_in, const int* in_sizes, int n_in,
                              void* d_out, int out_size)
{
    const float* x  = (const float*)d_in[0];
    const float* Wq = (const float*)d_in[1];
    const float* Wk = (const float*)d_in[2];
    const float* Wv = (const float*)d_in[3];
    const float* Wo = (const float*)d_in[4];

    float *qp, *kp, *vp, *op;
    cudaGetSymbolAddress((void**)&qp, g_q);
    cudaGetSymbolAddress((void**)&kp, g_k);
    cudaGetSymbolAddress((void**)&vp, g_v);
    cudaGetSymbolAddress((void**)&op, g_o);

    static int smem_set = 0;
    if (!smem_set) {
        cudaFuncSetAttribute(flash_tc,
                             cudaFuncAttributeMaxDynamicSharedMemorySize,
                             FLASH_SMEM);
        smem_set = 1;
    }

    dim3 gg(CC / GBN, MM / GBM);   // (8, 64)
    mgemm<<<gg, 256>>>(x, Wq, qp);
    mgemm<<<gg, 256>>>(x, Wk, kp);
    mgemm<<<gg, 256>>>(x, Wv, vp);

    rope2<<<dim3(TT, BB), 512>>>();

    flash_tc<<<dim3(TT / 64, BB * HH), 128, FLASH_SMEM>>>();

    mgemm<<<gg, 256>>>(op, Wo, (float*)d_out);

    // ---- capture-guarded host verification; rc=3 only on failure ------------
    cudaStreamCaptureStatus csx = cudaStreamCaptureStatusNone;
    cudaStreamIsCapturing(0, &csx);
    if (csx != cudaStreamCaptureStatusNone) return;

    cudaError_t e = cudaDeviceSynchronize();
    if (e != cudaSuccess) {
        printf("[HC] pipeline error: %s\n", cudaGetErrorString(e));
        fflush(stdout); exit(3);
    }
    int bad = 0;

    float dbg[16];
    cudaMemcpyFromSymbol(dbg, g_dbg, 16 * 4, 0);
    for (int j = 0; j < 4; j++) {
        double ang = (double)h_inv[j];
        if (fabs(dbg[2 * j] - cos(ang)) > 2e-3 || fabs(dbg[2 * j + 1] - sin(ang)) > 2e-3) {
            printf("[HC] probe j=%d got c=%.6g s=%.6g exp c=%.6g s=%.6g\n",
                   j, dbg[2 * j], dbg[2 * j + 1], cos(ang), sin(ang));
            bad++;
        }
    }
    cudaMemcpyFromSymbol(hA, g_q, 1024 * 4, 0);
    cudaMemcpyFromSymbol(hB, g_q2, 1024 * 4, 0);
    for (int ch = 0; ch < 1024 && bad < 8; ch++)
        if (fabsf(hA[ch] - hB[ch]) > 1e-5f) {
            printf("[HC] rope t0 ch=%d q=%.6g q2=%.6g\n", ch, hA[ch], hB[ch]);
            bad++;
        }
    cudaMemcpyFromSymbol(hA, g_q, 1024 * 4, (size_t)CC * 4);
    cudaMemcpyFromSymbol(hB, g_q2, 1024 * 4, (size_t)CC * 4);
    for (int h = 0; h < HH && bad < 8; h++)
        for (int j = 0; j < 32 && bad < 8; j++) {
            int ch = h * DD + j;
            double c = cos((double)h_inv[j]), s = sin((double)h_inv[j]);
            double e1 = hA[ch] * c - hA[ch + 32] * s;
            double e2 = hA[ch + 32] * c + hA[ch] * s;
            if (fabs(e1 - hB[ch]) > 1e-3 || fabs(e2 - hB[ch + 32]) > 1e-3) {
                printf("[HC] rope t1 h=%d j=%d got(%.6g,%.6g) exp(%.6g,%.6g)\n",
                       h, j, hB[ch], hB[ch + 32], e1, e2);
                bad++;
            }
        }
    cudaMemcpyFromSymbol(hC, g_o, 1024 * 4, 0);
    cudaMemcpyFromSymbol(hD, g_v, 1024 * 4, 0);
    for (int ch = 0; ch < 1024 && bad < 8; ch++)
        if (fabsf(hC[ch] - hD[ch]) > 2e-3f * (fabsf(hD[ch]) + 1e-1f)) {
            printf("[HC] attn t0 ch=%d o=%.6g v=%.6g\n", ch, hC[ch], hD[ch]);
            bad++;
        }
    {
        cudaMemcpyFromSymbol(hA, g_q2, 1024 * 4, (size_t)CC * 4);
        cudaMemcpyFromSymbol(hB, g_k2, 1024 * 4, 0);
        cudaMemcpyFromSymbol(hC, g_k2, 1024 * 4, (size_t)CC * 4);
        cudaMemcpyFromSymbol(hD, g_v,  1024 * 4, 0);
        cudaMemcpyFromSymbol(hV1, g_v, 1024 * 4, (size_t)CC * 4);
        static float ho1[1024];
        cudaMemcpyFromSymbol(ho1, g_o, 1024 * 4, (size_t)CC * 4);
        for (int h = 0; h < HH && bad < 8; h++) {
            double s0 = 0, s1 = 0;
            for (int d = 0; d < DD; d++) {
                s0 += (double)hA[h * DD + d] * hB[h * DD + d];
                s1 += (double)hA[h * DD + d] * hC[h * DD + d];
            }
            s0 *= 0.125; s1 *= 0.125;
            double m = s0 > s1 ? s0 : s1;
            double p0 = exp(s0 - m), p1 = exp(s1 - m), Z = p0 + p1;
            for (int d = 0; d < DD && bad < 8; d++) {
                double oe = (p0 * hD[h * DD + d] + p1 * hV1[h * DD + d]) / Z;
                if (fabs(oe - ho1[h * DD + d]) > 3e-3) {
                    printf("[HC] attn t1 h=%d d=%d got %.6g exp %.6g\n",
                           h, d, ho1[h * DD + d], oe);
                    bad++;
                }
            }
        }
    }
    {
        cudaMemcpyFromSymbol(hC, g_o, 1024 * 4, 0);
        cudaMemcpy(hE, Wo, 4096 * 4, cudaMemcpyDeviceToHost);
        float hout[4];
        cudaMemcpy(hout, d_out, 16, cudaMemcpyDeviceToHost);
        for (int r = 0; r < 4; r++) {
            double ex = 0;
            for (int k = 0; k < 1024; k++) ex += (double)hC[k] * hE[r * 1024 + k];
            if (fabs(ex - hout[r]) > 2e-3 * (fabs(ex) + 1.0)) {
                printf("[HC] out0 r=%d got %.6g exp %.6g\n", r, hout[r], ex);
                bad++;
            }
        }
    }
    if (bad) { printf("[HC] FAILED %d checks\n", bad); fflush(stdout); exit(3); }
}

// round 12
// speedup vs baseline: 3.1394x; 1.2243x over previous
#include <cuda_runtime.h>
#include <cstdio>
#include <cstdlib>
#include <math.h>

#define BB 2
#define TT 4096
#define CC 1024
#define HH 16
#define DD 64
#define MM (BB*TT)   // 8192

// ---------------- scratch -----------------------------------------------------
__device__ float g_q[(size_t)MM * CC];
__device__ float g_k[(size_t)MM * CC];
__device__ float g_v[(size_t)MM * CC];
__device__ float g_q2[(size_t)MM * CC];
__device__ float g_k2[(size_t)MM * CC];
__device__ float g_o[(size_t)MM * CC];
__device__ float g_dbg[16];

__constant__ float c_inv[32] = {
    1.0f,            0.749894209f,   0.562341325f,   0.421696503f,
    0.316227766f,    0.237137371f,   0.177827941f,   0.133352143f,
    0.1f,            0.0749894209f,  0.0562341325f,  0.0421696503f,
    0.0316227766f,   0.0237137371f,  0.0177827941f,  0.0133352143f,
    0.01f,           0.00749894209f, 0.00562341325f, 0.00421696503f,
    0.00316227766f,  0.00237137371f, 0.00177827941f, 0.00133352143f,
    0.001f,          0.000749894209f,0.000562341325f,0.000421696503f,
    0.000316227766f, 0.000237137371f,0.000177827941f,0.000133352143f
};
static const float h_inv[32] = {
    1.0f,            0.749894209f,   0.562341325f,   0.421696503f,
    0.316227766f,    0.237137371f,   0.177827941f,   0.133352143f,
    0.1f,            0.0749894209f,  0.0562341325f,  0.0421696503f,
    0.0316227766f,   0.0237137371f,  0.0177827941f,  0.0133352143f,
    0.01f,           0.00749894209f, 0.00562341325f, 0.00421696503f,
    0.00316227766f,  0.00237137371f, 0.00177827941f, 0.00133352143f,
    0.001f,          0.000749894209f,0.000562341325f,0.000421696503f,
    0.000316227766f, 0.000237137371f,0.000177827941f,0.000133352143f
};

__device__ __forceinline__ void safe_sincos(float ang, float* c, float* s)
{
    float k = rintf(ang * 0.159154943091895f);
    float r = fmaf(-k, 6.28318530717958f, ang);
    r = fmaf(-k, -1.7484556e-07f, r);
    sincosf(r, s, c);                     // CUDA: sin first, cos second!
}

__device__ __forceinline__ unsigned f2tf32(float x)
{
    unsigned r;
    asm("cvt.rna.tf32.f32 %0, %1;" : "=r"(r) : "f"(x));
    return r;
}

// FMA-only 2^y for y <= 0; no MUFU.
__device__ __forceinline__ float fexp2(float y)
{
    y = fmaxf(y, -100.0f);
    float z = y + 12582912.0f;
    int   i = __float_as_int(z) - 0x4B400000;
    float f = y - (z - 12582912.0f);
    float p =           0.0013333558f;
    p = fmaf(p, f, 0.0096181291f);
    p = fmaf(p, f, 0.0555041087f);
    p = fmaf(p, f, 0.2402265069f);
    p = fmaf(p, f, 0.6931471806f);
    p = fmaf(p, f, 1.0f);
    return __int_as_float(__float_as_int(p) + (i << 23));
}

#define MMA_TF32(acc, a0, a1, a2, a3, b0, b1)                                  \
    asm volatile(                                                              \
        "mma.sync.aligned.m16n8k8.row.col.f32.tf32.tf32.f32 "                  \
        "{%0,%1,%2,%3}, {%4,%5,%6,%7}, {%8,%9}, {%0,%1,%2,%3};"                \
        : "+f"(acc[0]), "+f"(acc[1]), "+f"(acc[2]), "+f"(acc[3])               \
        : "r"(a0), "r"(a1), "r"(a2), "r"(a3), "r"(b0), "r"(b1))

__device__ __forceinline__ void cpa16(unsigned saddr, const void* gptr)
{
    asm volatile("cp.async.ca.shared.global [%0], [%1], 16;"
                 :: "r"(saddr), "l"(gptr) : "memory");
}
#define CP_COMMIT() asm volatile("cp.async.commit_group;" ::: "memory")
#define CP_WAIT(N)  asm volatile("cp.async.wait_group %0;" :: "n"(N) : "memory")

// ---------------- pipelined TF32 GEMM: C[m,n] = sum_k A[m,k]*W[n,k] ----------
// CTA 128x128, BK=32, cp.async double buffer. smem [m][k] fp32 row-major,
// XOR swizzle k ^= (m&7)<<2 (16B-aligned chunks, conflict-free fragment LDS).
// Fragments tf32-converted (cvt.rna) at load time -> numerics == R10.
#define GBM 128
#define GBN 128
#define BK2 32
#define STG_F (128 * BK2)                  // floats per matrix per stage
#define SW(m, k) ((m) * BK2 + (((k) ^ (((m) & 7) << 2)) & 31))
#define GEMM_SMEM (4 * STG_F * 4)          // 2 stages x (A+B) x 16KB = 64KB

__global__ __launch_bounds__(256)
void pgemm(const float* __restrict__ A, const float* __restrict__ W,
           float* __restrict__ Cout)
{
    extern __shared__ float gsm[];
    float* As = gsm;                        // [stage][SW(m,k)]
    float* Bs = gsm + 2 * STG_F;

    const int tid  = threadIdx.x;
    const int lane = tid & 31;
    const int w    = tid >> 5;
    const int wm   = (w >> 1) * 32;
    const int wn   = (w & 1) * 64;
    const int m0 = blockIdx.y * GBM;
    const int n0 = blockIdx.x * GBN;
    const int lq = lane >> 2;
    const int lr = lane & 3;

    const unsigned sA = (unsigned)__cvta_generic_to_shared(As);
    const unsigned sB = (unsigned)__cvta_generic_to_shared(Bs);

    float c[2][8][4];
#pragma unroll
    for (int mi = 0; mi < 2; mi++)
#pragma unroll
        for (int ni = 0; ni < 8; ni++)
#pragma unroll
            for (int r = 0; r < 4; r++) c[mi][ni][r] = 0.f;

    // stage loader: 1024 16B-chunks per matrix, 256 thr -> 4 each
#define STAGE_LOAD(stg, kbase)                                                 \
    do {                                                                       \
        _Pragma("unroll")                                                      \
        for (int it = 0; it < 4; it++) {                                       \
            int lin = tid + it * 256;                                          \
            int row = lin >> 3;                                                \
            int kk  = (lin & 7) << 2;                                          \
            cpa16(sA + ((stg) * STG_F + SW(row, kk)) * 4,                      \
                  &A[(size_t)(m0 + row) * CC + (kbase) + kk]);                 \
            cpa16(sB + ((stg) * STG_F + SW(row, kk)) * 4,                      \
                  &W[(size_t)(n0 + row) * CC + (kbase) + kk]);                 \
        }                                                                      \
    } while (0)

    STAGE_LOAD(0, 0);
    CP_COMMIT();

    int buf = 0;
    for (int k0 = 0; k0 < CC; k0 += BK2) {
        if (k0 + BK2 < CC) {
            STAGE_LOAD(buf ^ 1, k0 + BK2);
            CP_COMMIT();
            CP_WAIT(1);
        } else {
            CP_WAIT(0);
        }
        __syncthreads();

        const float* Ab = As + buf * STG_F;
        const float* Bb = Bs + buf * STG_F;
#pragma unroll
        for (int ks = 0; ks < BK2; ks += 8) {
            unsigned af[2][4];
#pragma unroll
            for (int mi = 0; mi < 2; mi++) {
                int rlo = wm + mi * 16 + lq;
                af[mi][0] = f2tf32(Ab[SW(rlo,     ks + lr)]);
                af[mi][1] = f2tf32(Ab[SW(rlo + 8, ks + lr)]);
                af[mi][2] = f2tf32(Ab[SW(rlo,     ks + 4 + lr)]);
                af[mi][3] = f2tf32(Ab[SW(rlo + 8, ks + 4 + lr)]);
            }
            unsigned bf[8][2];
#pragma unroll
            for (int ni = 0; ni < 8; ni++) {
                int col = wn + ni * 8 + lq;
                bf[ni][0] = f2tf32(Bb[SW(col, ks + lr)]);
                bf[ni][1] = f2tf32(Bb[SW(col, ks + 4 + lr)]);
            }
#pragma unroll
            for (int mi = 0; mi < 2; mi++)
#pragma unroll
                for (int ni = 0; ni < 8; ni++)
                    MMA_TF32(c[mi][ni], af[mi][0], af[mi][1], af[mi][2], af[mi][3],
                             bf[ni][0], bf[ni][1]);
        }
        __syncthreads();
        buf ^= 1;
    }

#pragma unroll
    for (int mi = 0; mi < 2; mi++) {
        int rlo = m0 + wm + mi * 16 + lq;
#pragma unroll
        for (int ni = 0; ni < 8; ni++) {
            int cc = n0 + wn + ni * 8 + 2 * lr;
            *(float2*)&Cout[(size_t)rlo * CC + cc] =
                make_float2(c[mi][ni][0], c[mi][ni][1]);
            *(float2*)&Cout[(size_t)(rlo + 8) * CC + cc] =
                make_float2(c[mi][ni][2], c[mi][ni][3]);
        }
    }
#undef STAGE_LOAD
}

// ---------------- RoPE --------------------------------------------------------
__global__ __launch_bounds__(512) void rope2()
{
    const int t = blockIdx.x;
    const int b = blockIdx.y;
    const int h = threadIdx.x >> 5;
    const int j = threadIdx.x & 31;

    float ang = (float)t * c_inv[j];
    float c, s;
    safe_sincos(ang, &c, &s);

    if (t == 1 && b == 0 && threadIdx.x < 4) {
        g_dbg[2 * threadIdx.x]     = c;
        g_dbg[2 * threadIdx.x + 1] = s;
    }

    const size_t row = ((size_t)b * TT + t) * CC;
    const int ch = h * DD + j;
    float a1 = g_q[row + ch], a2 = g_q[row + ch + 32];
    g_q2[row + ch]      = a1 * c - a2 * s;
    g_q2[row + ch + 32] = a2 * c + a1 * s;
    a1 = g_k[row + ch]; a2 = g_k[row + ch + 32];
    g_k2[row + ch]      = a1 * c - a2 * s;
    g_k2[row + ch + 32] = a2 * c + a1 * s;
}

// ---------------- tensor-core flash attention (verified R11) -----------------
#define QLD 68
#define VLD 72
#define FLASH_SMEM ((3 * 64 * QLD + 64 * VLD) * 4)   // 70656 B

__global__ __launch_bounds__(128)
void flash_tc()
{
    extern __shared__ unsigned fsm[];
    unsigned* Qs = fsm;
    unsigned* Ks = fsm + 64 * QLD;
    unsigned* Ps = fsm + 2 * 64 * QLD;
    unsigned* Vs = fsm + 3 * 64 * QLD;

    const int tid  = threadIdx.x;
    const int lane = tid & 31;
    const int strip = (tid >> 5) * 16;
    const int lq = lane >> 2, lr = lane & 3;

    const int bh = blockIdx.y;
    const int b = bh >> 4, h = bh & 15;
    const int qb = gridDim.x - 1 - blockIdx.x;
    const int t0q = qb * 64;
    const size_t base = (size_t)b * TT * CC + h * DD;

    const float qsc = 0.125f * 1.44269504f;
#pragma unroll
    for (int it = 0; it < 8; it++) {
        int lin = tid + it * 128;
        int row = lin >> 4, c4 = (lin & 15) << 2;
        float4 a = *(const float4*)&g_q2[base + (size_t)(t0q + row) * CC + c4];
        *(uint4*)&Qs[row * QLD + c4] =
            make_uint4(f2tf32(a.x * qsc), f2tf32(a.y * qsc),
                       f2tf32(a.z * qsc), f2tf32(a.w * qsc));
    }

    float m_i[2] = {-INFINITY, -INFINITY};
    float l_i[2] = {0.f, 0.f};
    float oa[8][4];
#pragma unroll
    for (int ni = 0; ni < 8; ni++)
#pragma unroll
        for (int r = 0; r < 4; r++) oa[ni][r] = 0.f;

    for (int jt = 0; jt <= qb; jt++) {
        __syncthreads();
        const int t0k = jt * 64;
#pragma unroll
        for (int it = 0; it < 8; it++) {
            int lin = tid + it * 128;
            int row = lin >> 4, c4 = (lin & 15) << 2;
            float4 kv = *(const float4*)&g_k2[base + (size_t)(t0k + row) * CC + c4];
            *(uint4*)&Ks[row * QLD + c4] =
                make_uint4(f2tf32(kv.x), f2tf32(kv.y), f2tf32(kv.z), f2tf32(kv.w));
            float4 vv = *(const float4*)&g_v[base + (size_t)(t0k + row) * CC + c4];
            *(uint4*)&Vs[row * VLD + c4] =
                make_uint4(f2tf32(vv.x), f2tf32(vv.y), f2tf32(vv.z), f2tf32(vv.w));
        }
        __syncthreads();

        float sa[8][4];
#pragma unroll
        for (int ni = 0; ni < 8; ni++)
#pragma unroll
            for (int r = 0; r < 4; r++) sa[ni][r] = 0.f;

#pragma unroll
        for (int ks = 0; ks < 64; ks += 8) {
            unsigned a0 = Qs[(strip + lq) * QLD + ks + lr];
            unsigned a1 = Qs[(strip + lq + 8) * QLD + ks + lr];
            unsigned a2 = Qs[(strip + lq) * QLD + ks + 4 + lr];
            unsigned a3 = Qs[(strip + lq + 8) * QLD + ks + 4 + lr];
#pragma unroll
            for (int ni = 0; ni < 8; ni++) {
                unsigned b0 = Ks[(ni * 8 + lq) * QLD + ks + lr];
                unsigned b1 = Ks[(ni * 8 + lq) * QLD + ks + 4 + lr];
                MMA_TF32(sa[ni], a0, a1, a2, a3, b0, b1);
            }
        }

        if (jt == qb) {
            int r0 = strip + lq, r1 = r0 + 8;
#pragma unroll
            for (int ni = 0; ni < 8; ni++) {
                int col = ni * 8 + 2 * lr;
                if (col     > r0) sa[ni][0] = -1e30f;
                if (col + 1 > r0) sa[ni][1] = -1e30f;
                if (col     > r1) sa[ni][2] = -1e30f;
                if (col + 1 > r1) sa[ni][3] = -1e30f;
            }
        }

#pragma unroll
        for (int r = 0; r < 2; r++) {
            float mx = fmaxf(sa[0][2 * r], sa[0][2 * r + 1]);
#pragma unroll
            for (int ni = 1; ni < 8; ni++)
                mx = fmaxf(mx, fmaxf(sa[ni][2 * r], sa[ni][2 * r + 1]));
            mx = fmaxf(mx, __shfl_xor_sync(0xffffffffu, mx, 1));
            mx = fmaxf(mx, __shfl_xor_sync(0xffffffffu, mx, 2));
            float mnew  = fmaxf(m_i[r], mx);
            float alpha = fexp2(m_i[r] - mnew);
            m_i[r] = mnew;
            float sum = 0.f;
            int prow = (strip + lq + 8 * r) * QLD;
#pragma unroll
            for (int ni = 0; ni < 8; ni++) {
                float p0 = fexp2(sa[ni][2 * r] - mnew);
                float p1 = fexp2(sa[ni][2 * r + 1] - mnew);
                sum += p0 + p1;
                Ps[prow + ni * 8 + 2 * lr]     = f2tf32(p0);
                Ps[prow + ni * 8 + 2 * lr + 1] = f2tf32(p1);
            }
            sum += __shfl_xor_sync(0xffffffffu, sum, 1);
            sum += __shfl_xor_sync(0xffffffffu, sum, 2);
            l_i[r] = l_i[r] * alpha + sum;
#pragma unroll
            for (int ni = 0; ni < 8; ni++) {
                oa[ni][2 * r]     *= alpha;
                oa[ni][2 * r + 1] *= alpha;
            }
        }
        __syncwarp();

#pragma unroll
        for (int ks = 0; ks < 64; ks += 8) {
            unsigned a0 = Ps[(strip + lq) * QLD + ks + lr];
            unsigned a1 = Ps[(strip + lq + 8) * QLD + ks + lr];
            unsigned a2 = Ps[(strip + lq) * QLD + ks + 4 + lr];
            unsigned a3 = Ps[(strip + lq + 8) * QLD + ks + 4 + lr];
#pragma unroll
            for (int ni = 0; ni < 8; ni++) {
                unsigned b0 = Vs[(ks + lr) * VLD + ni * 8 + lq];
                unsigned b1 = Vs[(ks + 4 + lr) * VLD + ni * 8 + lq];
                MMA_TF32(oa[ni], a0, a1, a2, a3, b0, b1);
            }
        }
    }

    float inv0 = 1.f / l_i[0], inv1 = 1.f / l_i[1];
    int t0 = t0q + strip + lq;
#pragma unroll
    for (int ni = 0; ni < 8; ni++) {
        int d = ni * 8 + 2 * lr;
        *(float2*)&g_o[base + (size_t)t0 * CC + d] =
            make_float2(oa[ni][0] * inv0, oa[ni][1] * inv0);
        *(float2*)&g_o[base + (size_t)(t0 + 8) * CC + d] =
            make_float2(oa[ni][2] * inv1, oa[ni][3] * inv1);
    }
}

// ---------------- launch -----------------------------------------------------
static float hA[1024], hB[1024], hC[1024], hD[1024], hE[4096], hV1[1024];

extern "C" void kernel_launch(void* const* d_in, const int* in_sizes, int n_in,
                              void* d_out, int out_size)
{
    const float* x  = (const float*)d_in[0];
    const float* Wq = (const float*)d_in[1];
    const float* Wk = (const float*)d_in[2];
    const float* Wv = (const float*)d_in[3];
    const float* Wo = (const float*)d_in[4];

    float *qp, *kp, *vp, *op;
    cudaGetSymbolAddress((void**)&qp, g_q);
    cudaGetSymbolAddress((void**)&kp, g_k);
    cudaGetSymbolAddress((void**)&vp, g_v);
    cudaGetSymbolAddress((void**)&op, g_o);

    static int smem_set = 0;
    if (!smem_set) {
        cudaFuncSetAttribute(flash_tc,
                             cudaFuncAttributeMaxDynamicSharedMemorySize,
                             FLASH_SMEM);
        cudaFuncSetAttribute(pgemm,
                             cudaFuncAttributeMaxDynamicSharedMemorySize,
                             GEMM_SMEM);
        smem_set = 1;
    }

    dim3 gg(CC / GBN, MM / GBM);   // (8, 64)
    pgemm<<<gg, 256, GEMM_SMEM>>>(x, Wq, qp);
    pgemm<<<gg, 256, GEMM_SMEM>>>(x, Wk, kp);
    pgemm<<<gg, 256, GEMM_SMEM>>>(x, Wv, vp);

    rope2<<<dim3(TT, BB), 512>>>();

    flash_tc<<<dim3(TT / 64, BB * HH), 128, FLASH_SMEM>>>();

    pgemm<<<gg, 256, GEMM_SMEM>>>(op, Wo, (float*)d_out);

    // ---- capture-guarded host verification; rc=3 only on failure ------------
    cudaStreamCaptureStatus csx = cudaStreamCaptureStatusNone;
    cudaStreamIsCapturing(0, &csx);
    if (csx != cudaStreamCaptureStatusNone) return;

    cudaError_t e = cudaDeviceSynchronize();
    if (e != cudaSuccess) {
        printf("[HC] pipeline error: %s\n", cudaGetErrorString(e));
        fflush(stdout); exit(3);
    }
    int bad = 0;

    float dbg[16];
    cudaMemcpyFromSymbol(dbg, g_dbg, 16 * 4, 0);
    for (int j = 0; j < 4; j++) {
        double ang = (double)h_inv[j];
        if (fabs(dbg[2 * j] - cos(ang)) > 2e-3 || fabs(dbg[2 * j + 1] - sin(ang)) > 2e-3) {
            printf("[HC] probe j=%d got c=%.6g s=%.6g exp c=%.6g s=%.6g\n",
                   j, dbg[2 * j], dbg[2 * j + 1], cos(ang), sin(ang));
            bad++;
        }
    }
    cudaMemcpyFromSymbol(hA, g_q, 1024 * 4, 0);
    cudaMemcpyFromSymbol(hB, g_q2, 1024 * 4, 0);
    for (int ch = 0; ch < 1024 && bad < 8; ch++)
        if (fabsf(hA[ch] - hB[ch]) > 1e-5f) {
            printf("[HC] rope t0 ch=%d q=%.6g q2=%.6g\n", ch, hA[ch], hB[ch]);
            bad++;
        }
    cudaMemcpyFromSymbol(hA, g_q, 1024 * 4, (size_t)CC * 4);
    cudaMemcpyFromSymbol(hB, g_q2, 1024 * 4, (size_t)CC * 4);
    for (int h = 0; h < HH && bad < 8; h++)
        for (int j = 0; j < 32 && bad < 8; j++) {
            int ch = h * DD + j;
            double c = cos((double)h_inv[j]), s = sin((double)h_inv[j]);
            double e1 = hA[ch] * c - hA[ch + 32] * s;
            double e2 = hA[ch + 32] * c + hA[ch] * s;
            if (fabs(e1 - hB[ch]) > 1e-3 || fabs(e2 - hB[ch + 32]) > 1e-3) {
                printf("[HC] rope t1 h=%d j=%d got(%.6g,%.6g) exp(%.6g,%.6g)\n",
                       h, j, hB[ch], hB[ch + 32], e1, e2);
                bad++;
            }
        }
    cudaMemcpyFromSymbol(hC, g_o, 1024 * 4, 0);
    cudaMemcpyFromSymbol(hD, g_v, 1024 * 4, 0);
    for (int ch = 0; ch < 1024 && bad < 8; ch++)
        if (fabsf(hC[ch] - hD[ch]) > 2e-3f * (fabsf(hD[ch]) + 1e-1f)) {
            printf("[HC] attn t0 ch=%d o=%.6g v=%.6g\n", ch, hC[ch], hD[ch]);
            bad++;
        }
    {
        cudaMemcpyFromSymbol(hA, g_q2, 1024 * 4, (size_t)CC * 4);
        cudaMemcpyFromSymbol(hB, g_k2, 1024 * 4, 0);
        cudaMemcpyFromSymbol(hC, g_k2, 1024 * 4, (size_t)CC * 4);
        cudaMemcpyFromSymbol(hD, g_v,  1024 * 4, 0);
        cudaMemcpyFromSymbol(hV1, g_v, 1024 * 4, (size_t)CC * 4);
        static float ho1[1024];
        cudaMemcpyFromSymbol(ho1, g_o, 1024 * 4, (size_t)CC * 4);
        for (int h = 0; h < HH && bad < 8; h++) {
            double s0 = 0, s1 = 0;
            for (int d = 0; d < DD; d++) {
                s0 += (double)hA[h * DD + d] * hB[h * DD + d];
                s1 += (double)hA[h * DD + d] * hC[h * DD + d];
            }
            s0 *= 0.125; s1 *= 0.125;
            double m = s0 > s1 ? s0 : s1;
            double p0 = exp(s0 - m), p1 = exp(s1 - m), Z = p0 + p1;
            for (int d = 0; d < DD && bad < 8; d++) {
                double oe = (p0 * hD[h * DD + d] + p1 * hV1[h * DD + d]) / Z;
                if (fabs(oe - ho1[h * DD + d]) > 3e-3) {
                    printf("[HC] attn t1 h=%d d=%d got %.6g exp %.6g\n",
                           h, d, ho1[h * DD + d], oe);
                    bad++;
                }
            }
        }
    }
    {
        cudaMemcpyFromSymbol(hC, g_o, 1024 * 4, 0);
        cudaMemcpy(hE, Wo, 4096 * 4, cudaMemcpyDeviceToHost);
        float hout[4];
        cudaMemcpy(hout, d_out, 16, cudaMemcpyDeviceToHost);
        for (int r = 0; r < 4; r++) {
            double ex = 0;
            for (int k = 0; k < 1024; k++) ex += (double)hC[k] * hE[r * 1024 + k];
            if (fabs(ex - hout[r]) > 2e-3 * (fabs(ex) + 1.0)) {
                printf("[HC] out0 r=%d got %.6g exp %.6g\n", r, hout[r], ex);
                bad++;
            }
        }
    }
    if (bad) { printf("[HC] FAILED %d checks\n", bad); fflush(stdout); exit(3); }
}

// round 13
// speedup vs baseline: 3.2726x; 1.0424x over previous
#include <cuda_runtime.h>
#include <cstdio>
#include <cstdlib>
#include <math.h>

#define BB 2
#define TT 4096
#define CC 1024
#define HH 16
#define DD 64
#define MM (BB*TT)   // 8192

// ---------------- scratch -----------------------------------------------------
__device__ float g_xt[(size_t)MM * CC];   // tf32-rounded x
__device__ float g_wt[4][(size_t)CC * CC];// tf32-rounded Wq,Wk,Wv,Wo
__device__ float g_q2[(size_t)MM * CC];   // roped q  [B,T,C]
__device__ float g_k2[(size_t)MM * CC];   // roped k
__device__ float g_v [(size_t)MM * CC];
__device__ float g_o [(size_t)MM * CC];   // attention out (tf32-rounded)

__constant__ float c_inv[32] = {
    1.0f,            0.749894209f,   0.562341325f,   0.421696503f,
    0.316227766f,    0.237137371f,   0.177827941f,   0.133352143f,
    0.1f,            0.0749894209f,  0.0562341325f,  0.0421696503f,
    0.0316227766f,   0.0237137371f,  0.0177827941f,  0.0133352143f,
    0.01f,           0.00749894209f, 0.00562341325f, 0.00421696503f,
    0.00316227766f,  0.00237137371f, 0.00177827941f, 0.00133352143f,
    0.001f,          0.000749894209f,0.000562341325f,0.000421696503f,
    0.000316227766f, 0.000237137371f,0.000177827941f,0.000133352143f
};
static const float h_inv[32] = {
    1.0f,            0.749894209f,   0.562341325f,   0.421696503f,
    0.316227766f,    0.237137371f,   0.177827941f,   0.133352143f,
    0.1f,            0.0749894209f,  0.0562341325f,  0.0421696503f,
    0.0316227766f,   0.0237137371f,  0.0177827941f,  0.0133352143f,
    0.01f,           0.00749894209f, 0.00562341325f, 0.00421696503f,
    0.00316227766f,  0.00237137371f, 0.00177827941f, 0.00133352143f,
    0.001f,          0.000749894209f,0.000562341325f,0.000421696503f,
    0.000316227766f, 0.000237137371f,0.000177827941f,0.000133352143f
};

__device__ __forceinline__ void safe_sincos(float ang, float* c, float* s)
{
    float k = rintf(ang * 0.159154943091895f);
    float r = fmaf(-k, 6.28318530717958f, ang);
    r = fmaf(-k, -1.7484556e-07f, r);
    sincosf(r, s, c);                     // CUDA: sin first, cos second!
}

__device__ __forceinline__ unsigned f2tf32(float x)
{
    unsigned r;
    asm("cvt.rna.tf32.f32 %0, %1;" : "=r"(r) : "f"(x));
    return r;
}

// FMA-only 2^y for y <= 0; no MUFU.
__device__ __forceinline__ float fexp2(float y)
{
    y = fmaxf(y, -100.0f);
    float z = y + 12582912.0f;
    int   i = __float_as_int(z) - 0x4B400000;
    float f = y - (z - 12582912.0f);
    float p =           0.0013333558f;
    p = fmaf(p, f, 0.0096181291f);
    p = fmaf(p, f, 0.0555041087f);
    p = fmaf(p, f, 0.2402265069f);
    p = fmaf(p, f, 0.6931471806f);
    p = fmaf(p, f, 1.0f);
    return __int_as_float(__float_as_int(p) + (i << 23));
}

#define MMA_TF32(acc, a0, a1, a2, a3, b0, b1)                                  \
    asm volatile(                                                              \
        "mma.sync.aligned.m16n8k8.row.col.f32.tf32.tf32.f32 "                  \
        "{%0,%1,%2,%3}, {%4,%5,%6,%7}, {%8,%9}, {%0,%1,%2,%3};"                \
        : "+f"(acc[0]), "+f"(acc[1]), "+f"(acc[2]), "+f"(acc[3])               \
        : "r"(a0), "r"(a1), "r"(a2), "r"(a3), "r"(b0), "r"(b1))

__device__ __forceinline__ void cpa16(unsigned saddr, const void* gptr)
{
    asm volatile("cp.async.ca.shared.global [%0], [%1], 16;"
                 :: "r"(saddr), "l"(gptr) : "memory");
}
#define CP_COMMIT() asm volatile("cp.async.commit_group;" ::: "memory")
#define CP_WAIT(N)  asm volatile("cp.async.wait_group %0;" :: "n"(N) : "memory")

// ---------------- tf32 pre-rounding pass -------------------------------------
__global__ void cvt_tf32(const float* __restrict__ in, float* __restrict__ out)
{
    size_t i = ((size_t)blockIdx.x * blockDim.x + threadIdx.x) * 4;
    float4 v = *(const float4*)&in[i];
    uint4 r = make_uint4(f2tf32(v.x), f2tf32(v.y), f2tf32(v.z), f2tf32(v.w));
    *(uint4*)&out[i] = r;
}

// ---------------- pipelined TF32 GEMM, rope-fusable epilogue -----------------
// Inputs MUST be tf32-pre-rounded; fragments feed mma directly (no cvt).
#define GBM 128
#define GBN 128
#define BK2 32
#define STG_F (128 * BK2)
#define SW(m, k) ((m) * BK2 + (((k) ^ (((m) & 7) << 2)) & 31))
#define GEMM_SMEM (4 * STG_F * 4)          // 64KB

__global__ __launch_bounds__(256)
void pgemm(const float* __restrict__ A, const float* __restrict__ W,
           float* __restrict__ Cout, int do_rope)
{
    extern __shared__ float gsm[];
    float* As = gsm;
    float* Bs = gsm + 2 * STG_F;

    const int tid  = threadIdx.x;
    const int lane = tid & 31;
    const int w    = tid >> 5;
    const int wm   = (w >> 1) * 32;
    const int wn   = (w & 1) * 64;
    const int m0 = blockIdx.y * GBM;
    const int n0 = blockIdx.x * GBN;
    const int lq = lane >> 2;
    const int lr = lane & 3;

    const unsigned sA = (unsigned)__cvta_generic_to_shared(As);
    const unsigned sB = (unsigned)__cvta_generic_to_shared(Bs);

    float c[2][8][4];
#pragma unroll
    for (int mi = 0; mi < 2; mi++)
#pragma unroll
        for (int ni = 0; ni < 8; ni++)
#pragma unroll
            for (int r = 0; r < 4; r++) c[mi][ni][r] = 0.f;

#define STAGE_LOAD(stg, kbase)                                                 \
    do {                                                                       \
        _Pragma("unroll")                                                      \
        for (int it = 0; it < 4; it++) {                                       \
            int lin = tid + it * 256;                                          \
            int row = lin >> 3;                                                \
            int kk  = (lin & 7) << 2;                                          \
            cpa16(sA + ((stg) * STG_F + SW(row, kk)) * 4,                      \
                  &A[(size_t)(m0 + row) * CC + (kbase) + kk]);                 \
            cpa16(sB + ((stg) * STG_F + SW(row, kk)) * 4,                      \
                  &W[(size_t)(n0 + row) * CC + (kbase) + kk]);                 \
        }                                                                      \
    } while (0)

    STAGE_LOAD(0, 0);
    CP_COMMIT();

    int buf = 0;
    for (int k0 = 0; k0 < CC; k0 += BK2) {
        if (k0 + BK2 < CC) {
            STAGE_LOAD(buf ^ 1, k0 + BK2);
            CP_COMMIT();
            CP_WAIT(1);
        } else {
            CP_WAIT(0);
        }
        __syncthreads();

        const float* Ab = As + buf * STG_F;
        const float* Bb = Bs + buf * STG_F;
#pragma unroll
        for (int ks = 0; ks < BK2; ks += 8) {
            unsigned af[2][4];
#pragma unroll
            for (int mi = 0; mi < 2; mi++) {
                int rlo = wm + mi * 16 + lq;
                af[mi][0] = __float_as_uint(Ab[SW(rlo,     ks + lr)]);
                af[mi][1] = __float_as_uint(Ab[SW(rlo + 8, ks + lr)]);
                af[mi][2] = __float_as_uint(Ab[SW(rlo,     ks + 4 + lr)]);
                af[mi][3] = __float_as_uint(Ab[SW(rlo + 8, ks + 4 + lr)]);
            }
            unsigned bf[8][2];
#pragma unroll
            for (int ni = 0; ni < 8; ni++) {
                int col = wn + ni * 8 + lq;
                bf[ni][0] = __float_as_uint(Bb[SW(col, ks + lr)]);
                bf[ni][1] = __float_as_uint(Bb[SW(col, ks + 4 + lr)]);
            }
#pragma unroll
            for (int mi = 0; mi < 2; mi++)
#pragma unroll
                for (int ni = 0; ni < 8; ni++)
                    MMA_TF32(c[mi][ni], af[mi][0], af[mi][1], af[mi][2], af[mi][3],
                             bf[ni][0], bf[ni][1]);
        }
        __syncthreads();
        buf ^= 1;
    }

    // fused RoPE: warp N-tile (64 wide, 64-aligned) spans head pairs (j, j+32);
    // partner column lives at atom ni+4, same thread, same reg index.
    if (do_rope) {
#pragma unroll
        for (int mi = 0; mi < 2; mi++) {
            int rbase = m0 + wm + mi * 16 + lq;
#pragma unroll
            for (int rr = 0; rr < 2; rr++) {
                int t = (rbase + 8 * rr) & (TT - 1);
#pragma unroll
                for (int ni = 0; ni < 4; ni++) {
#pragma unroll
                    for (int c2 = 0; c2 < 2; c2++) {
                        int j = ni * 8 + 2 * lr + c2;
                        float cs, sn;
                        safe_sincos((float)t * c_inv[j], &cs, &sn);
                        int idx = 2 * rr + c2;
                        float a1 = c[mi][ni][idx], a2 = c[mi][ni + 4][idx];
                        c[mi][ni][idx]     = a1 * cs - a2 * sn;
                        c[mi][ni + 4][idx] = a2 * cs + a1 * sn;
                    }
                }
            }
        }
    }

#pragma unroll
    for (int mi = 0; mi < 2; mi++) {
        int rlo = m0 + wm + mi * 16 + lq;
#pragma unroll
        for (int ni = 0; ni < 8; ni++) {
            int cc = n0 + wn + ni * 8 + 2 * lr;
            *(float2*)&Cout[(size_t)rlo * CC + cc] =
                make_float2(c[mi][ni][0], c[mi][ni][1]);
            *(float2*)&Cout[(size_t)(rlo + 8) * CC + cc] =
                make_float2(c[mi][ni][2], c[mi][ni][3]);
        }
    }
#undef STAGE_LOAD
}

// ---------------- tensor-core flash attention (verified R11/R12) -------------
#define QLD 68
#define VLD 72
#define FLASH_SMEM ((3 * 64 * QLD + 64 * VLD) * 4)   // 70656 B

__global__ __launch_bounds__(128)
void flash_tc()
{
    extern __shared__ unsigned fsm[];
    unsigned* Qs = fsm;
    unsigned* Ks = fsm + 64 * QLD;
    unsigned* Ps = fsm + 2 * 64 * QLD;
    unsigned* Vs = fsm + 3 * 64 * QLD;

    const int tid  = threadIdx.x;
    const int lane = tid & 31;
    const int strip = (tid >> 5) * 16;
    const int lq = lane >> 2, lr = lane & 3;

    const int bh = blockIdx.y;
    const int b = bh >> 4, h = bh & 15;
    const int qb = gridDim.x - 1 - blockIdx.x;
    const int t0q = qb * 64;
    const size_t base = (size_t)b * TT * CC + h * DD;

    const float qsc = 0.125f * 1.44269504f;
#pragma unroll
    for (int it = 0; it < 8; it++) {
        int lin = tid + it * 128;
        int row = lin >> 4, c4 = (lin & 15) << 2;
        float4 a = *(const float4*)&g_q2[base + (size_t)(t0q + row) * CC + c4];
        *(uint4*)&Qs[row * QLD + c4] =
            make_uint4(f2tf32(a.x * qsc), f2tf32(a.y * qsc),
                       f2tf32(a.z * qsc), f2tf32(a.w * qsc));
    }

    float m_i[2] = {-INFINITY, -INFINITY};
    float l_i[2] = {0.f, 0.f};
    float oa[8][4];
#pragma unroll
    for (int ni = 0; ni < 8; ni++)
#pragma unroll
        for (int r = 0; r < 4; r++) oa[ni][r] = 0.f;

    for (int jt = 0; jt <= qb; jt++) {
        __syncthreads();
        const int t0k = jt * 64;
#pragma unroll
        for (int it = 0; it < 8; it++) {
            int lin = tid + it * 128;
            int row = lin >> 4, c4 = (lin & 15) << 2;
            float4 kv = *(const float4*)&g_k2[base + (size_t)(t0k + row) * CC + c4];
            *(uint4*)&Ks[row * QLD + c4] =
                make_uint4(f2tf32(kv.x), f2tf32(kv.y), f2tf32(kv.z), f2tf32(kv.w));
            float4 vv = *(const float4*)&g_v[base + (size_t)(t0k + row) * CC + c4];
            *(uint4*)&Vs[row * VLD + c4] =
                make_uint4(f2tf32(vv.x), f2tf32(vv.y), f2tf32(vv.z), f2tf32(vv.w));
        }
        __syncthreads();

        float sa[8][4];
#pragma unroll
        for (int ni = 0; ni < 8; ni++)
#pragma unroll
            for (int r = 0; r < 4; r++) sa[ni][r] = 0.f;

#pragma unroll
        for (int ks = 0; ks < 64; ks += 8) {
            unsigned a0 = Qs[(strip + lq) * QLD + ks + lr];
            unsigned a1 = Qs[(strip + lq + 8) * QLD + ks + lr];
            unsigned a2 = Qs[(strip + lq) * QLD + ks + 4 + lr];
            unsigned a3 = Qs[(strip + lq + 8) * QLD + ks + 4 + lr];
#pragma unroll
            for (int ni = 0; ni < 8; ni++) {
                unsigned b0 = Ks[(ni * 8 + lq) * QLD + ks + lr];
                unsigned b1 = Ks[(ni * 8 + lq) * QLD + ks + 4 + lr];
                MMA_TF32(sa[ni], a0, a1, a2, a3, b0, b1);
            }
        }

        if (jt == qb) {
            int r0 = strip + lq, r1 = r0 + 8;
#pragma unroll
            for (int ni = 0; ni < 8; ni++) {
                int col = ni * 8 + 2 * lr;
                if (col     > r0) sa[ni][0] = -1e30f;
                if (col + 1 > r0) sa[ni][1] = -1e30f;
                if (col     > r1) sa[ni][2] = -1e30f;
                if (col + 1 > r1) sa[ni][3] = -1e30f;
            }
        }

#pragma unroll
        for (int r = 0; r < 2; r++) {
            float mx = fmaxf(sa[0][2 * r], sa[0][2 * r + 1]);
#pragma unroll
            for (int ni = 1; ni < 8; ni++)
                mx = fmaxf(mx, fmaxf(sa[ni][2 * r], sa[ni][2 * r + 1]));
            mx = fmaxf(mx, __shfl_xor_sync(0xffffffffu, mx, 1));
            mx = fmaxf(mx, __shfl_xor_sync(0xffffffffu, mx, 2));
            float mnew  = fmaxf(m_i[r], mx);
            float alpha = fexp2(m_i[r] - mnew);
            m_i[r] = mnew;
            float sum = 0.f;
            int prow = (strip + lq + 8 * r) * QLD;
#pragma unroll
            for (int ni = 0; ni < 8; ni++) {
                float p0 = fexp2(sa[ni][2 * r] - mnew);
                float p1 = fexp2(sa[ni][2 * r + 1] - mnew);
                sum += p0 + p1;
                Ps[prow + ni * 8 + 2 * lr]     = f2tf32(p0);
                Ps[prow + ni * 8 + 2 * lr + 1] = f2tf32(p1);
            }
            sum += __shfl_xor_sync(0xffffffffu, sum, 1);
            sum += __shfl_xor_sync(0xffffffffu, sum, 2);
            l_i[r] = l_i[r] * alpha + sum;
#pragma unroll
            for (int ni = 0; ni < 8; ni++) {
                oa[ni][2 * r]     *= alpha;
                oa[ni][2 * r + 1] *= alpha;
            }
        }
        __syncwarp();

#pragma unroll
        for (int ks = 0; ks < 64; ks += 8) {
            unsigned a0 = Ps[(strip + lq) * QLD + ks + lr];
            unsigned a1 = Ps[(strip + lq + 8) * QLD + ks + lr];
            unsigned a2 = Ps[(strip + lq) * QLD + ks + 4 + lr];
            unsigned a3 = Ps[(strip + lq + 8) * QLD + ks + 4 + lr];
#pragma unroll
            for (int ni = 0; ni < 8; ni++) {
                unsigned b0 = Vs[(ks + lr) * VLD + ni * 8 + lq];
                unsigned b1 = Vs[(ks + 4 + lr) * VLD + ni * 8 + lq];
                MMA_TF32(oa[ni], a0, a1, a2, a3, b0, b1);
            }
        }
    }

    // epilogue: normalize + tf32-round (final GEMM consumes without cvt)
    float inv0 = 1.f / l_i[0], inv1 = 1.f / l_i[1];
    int t0 = t0q + strip + lq;
#pragma unroll
    for (int ni = 0; ni < 8; ni++) {
        int d = ni * 8 + 2 * lr;
        *(uint2*)&g_o[base + (size_t)t0 * CC + d] =
            make_uint2(f2tf32(oa[ni][0] * inv0), f2tf32(oa[ni][1] * inv0));
        *(uint2*)&g_o[base + (size_t)(t0 + 8) * CC + d] =
            make_uint2(f2tf32(oa[ni][2] * inv1), f2tf32(oa[ni][3] * inv1));
    }
}

// ---------------- launch -----------------------------------------------------
static float hA[1024], hB[1024], hC[1024], hD[1024], hV1[1024], ho1[1024];
static float hW[(size_t)CC * CC];   // 4MB host copy for verification
static float hx2[2 * CC];

extern "C" void kernel_launch(void* const* d_in, const int* in_sizes, int n_in,
                              void* d_out, int out_size)
{
    const float* x  = (const float*)d_in[0];
    const float* Wq = (const float*)d_in[1];
    const float* Wk = (const float*)d_in[2];
    const float* Wv = (const float*)d_in[3];
    const float* Wo = (const float*)d_in[4];

    float *xt, *wt, *q2, *k2, *vp, *op;
    cudaGetSymbolAddress((void**)&xt, g_xt);
    cudaGetSymbolAddress((void**)&wt, g_wt);
    cudaGetSymbolAddress((void**)&q2, g_q2);
    cudaGetSymbolAddress((void**)&k2, g_k2);
    cudaGetSymbolAddress((void**)&vp, g_v);
    cudaGetSymbolAddress((void**)&op, g_o);
    float* wt0 = wt;
    float* wt1 = wt + (size_t)CC * CC;
    float* wt2 = wt + 2 * (size_t)CC * CC;
    float* wt3 = wt + 3 * (size_t)CC * CC;

    static int smem_set = 0;
    if (!smem_set) {
        cudaFuncSetAttribute(flash_tc,
                             cudaFuncAttributeMaxDynamicSharedMemorySize,
                             FLASH_SMEM);
        cudaFuncSetAttribute(pgemm,
                             cudaFuncAttributeMaxDynamicSharedMemorySize,
                             GEMM_SMEM);
        smem_set = 1;
    }

    // pre-round to tf32 (RNA) once
    cvt_tf32<<<(MM * CC) / 1024, 256>>>(x, xt);
    cvt_tf32<<<(CC * CC) / 1024, 256>>>(Wq, wt0);
    cvt_tf32<<<(CC * CC) / 1024, 256>>>(Wk, wt1);
    cvt_tf32<<<(CC * CC) / 1024, 256>>>(Wv, wt2);
    cvt_tf32<<<(CC * CC) / 1024, 256>>>(Wo, wt3);

    dim3 gg(CC / GBN, MM / GBM);   // (8, 64)
    pgemm<<<gg, 256, GEMM_SMEM>>>(xt, wt0, q2, 1);   // Q + fused rope
    pgemm<<<gg, 256, GEMM_SMEM>>>(xt, wt1, k2, 1);   // K + fused rope
    pgemm<<<gg, 256, GEMM_SMEM>>>(xt, wt2, vp, 0);   // V

    flash_tc<<<dim3(TT / 64, BB * HH), 128, FLASH_SMEM>>>();

    pgemm<<<gg, 256, GEMM_SMEM>>>(op, wt3, (float*)d_out, 0);

    // ---- capture-guarded host verification; rc=3 only on failure ------------
    cudaStreamCaptureStatus csx = cudaStreamCaptureStatusNone;
    cudaStreamIsCapturing(0, &csx);
    if (csx != cudaStreamCaptureStatusNone) return;

    cudaError_t e = cudaDeviceSynchronize();
    if (e != cudaSuccess) {
        printf("[HC] pipeline error: %s\n", cudaGetErrorString(e));
        fflush(stdout); exit(3);
    }
    int bad = 0;

    // (1)+(2) q2 rows 0 and 1 vs host x.Wq^T (+rotation at t=1)
    cudaMemcpy(hW, Wq, (size_t)CC * CC * 4, cudaMemcpyDeviceToHost);
    cudaMemcpy(hx2, x, 2 * CC * 4, cudaMemcpyDeviceToHost);
    cudaMemcpyFromSymbol(hA, g_q2, 1024 * 4, 0);               // q2 row0
    cudaMemcpyFromSymbol(hB, g_q2, 1024 * 4, (size_t)CC * 4);  // q2 row1
    {
        static double raw1[1024];
        for (int ch = 0; ch < 1024; ch++) {
            double e0 = 0, e1 = 0;
            for (int k = 0; k < 1024; k++) {
                e0 += (double)hx2[k] * hW[(size_t)ch * CC + k];
                e1 += (double)hx2[CC + k] * hW[(size_t)ch * CC + k];
            }
            raw1[ch] = e1;
            if (fabs(e0 - hA[ch]) > 4e-3 * (fabs(e0) + 1.0) && bad < 8) {
                printf("[HC] q2 t0 ch=%d got %.6g exp %.6g\n", ch, hA[ch], e0);
                bad++;
            }
        }
        for (int h = 0; h < HH && bad < 8; h++)
            for (int j = 0; j < 32 && bad < 8; j++) {
                int ch = h * DD + j;
                double cq = cos((double)h_inv[j]), sq = sin((double)h_inv[j]);
                double r1 = raw1[ch] * cq - raw1[ch + 32] * sq;
                double r2 = raw1[ch + 32] * cq + raw1[ch] * sq;
                if (fabs(r1 - hB[ch]) > 4e-3 * (fabs(r1) + 1.0) ||
                    fabs(r2 - hB[ch + 32]) > 4e-3 * (fabs(r2) + 1.0)) {
                    printf("[HC] q2 t1 h=%d j=%d got(%.6g,%.6g) exp(%.6g,%.6g)\n",
                           h, j, hB[ch], hB[ch + 32], r1, r2);
                    bad++;
                }
            }
    }
    // (3) attention t=0: o == v
    cudaMemcpyFromSymbol(hC, g_o, 1024 * 4, 0);
    cudaMemcpyFromSymbol(hD, g_v, 1024 * 4, 0);
    for (int ch = 0; ch < 1024 && bad < 8; ch++)
        if (fabsf(hC[ch] - hD[ch]) > 2e-3f * (fabsf(hD[ch]) + 1e-1f)) {
            printf("[HC] attn t0 ch=%d o=%.6g v=%.6g\n", ch, hC[ch], hD[ch]);
            bad++;
        }
    // (4) attention t=1: two-key softmax vs host
    {
        cudaMemcpyFromSymbol(hA, g_q2, 1024 * 4, (size_t)CC * 4);
        cudaMemcpyFromSymbol(hB, g_k2, 1024 * 4, 0);
        cudaMemcpyFromSymbol(hC, g_k2, 1024 * 4, (size_t)CC * 4);
        cudaMemcpyFromSymbol(hD, g_v,  1024 * 4, 0);
        cudaMemcpyFromSymbol(hV1, g_v, 1024 * 4, (size_t)CC * 4);
        cudaMemcpyFromSymbol(ho1, g_o, 1024 * 4, (size_t)CC * 4);
        for (int h = 0; h < HH && bad < 8; h++) {
            double s0 = 0, s1 = 0;
            for (int d = 0; d < DD; d++) {
                s0 += (double)hA[h * DD + d] * hB[h * DD + d];
                s1 += (double)hA[h * DD + d] * hC[h * DD + d];
            }
            s0 *= 0.125; s1 *= 0.125;
            double m = s0 > s1 ? s0 : s1;
            double p0 = exp(s0 - m), p1 = exp(s1 - m), Z = p0 + p1;
            for (int d = 0; d < DD && bad < 8; d++) {
                double oe = (p0 * hD[h * DD + d] + p1 * hV1[h * DD + d]) / Z;
                if (fabs(oe - ho1[h * DD + d]) > 3e-3) {
                    printf("[HC] attn t1 h=%d d=%d got %.6g exp %.6g\n",
                           h, d, ho1[h * DD + d], oe);
                    bad++;
                }
            }
        }
    }
    // (5) final out[0,0:4] vs host dot
    {
        cudaMemcpyFromSymbol(hC, g_o, 1024 * 4, 0);
        cudaMemcpy(hW, Wo, 4096 * 4, cudaMemcpyDeviceToHost);  // Wo rows 0..3
        float hout[4];
        cudaMemcpy(hout, d_out, 16, cudaMemcpyDeviceToHost);
        for (int r = 0; r < 4; r++) {
            double ex = 0;
            for (int k = 0; k < 1024; k++) ex += (double)hC[k] * hW[r * 1024 + k];
            if (fabs(ex - hout[r]) > 2e-3 * (fabs(ex) + 1.0)) {
                printf("[HC] out0 r=%d got %.6g exp %.6g\n", r, hout[r], ex);
                bad++;
            }
        }
    }
    if (bad) { printf("[HC] FAILED %d checks\n", bad); fflush(stdout); exit(3); }
}